// round 14
// baseline (speedup 1.0000x reference)
#include <cuda_runtime.h>
#include <math_constants.h>

#define NROI   1500
#define NCLS   80          // foreground classes 1..80
#define NTOT   (NROI*NCLS) // 120000
#define SCORE_THRESH 0.05f
#define NMS_THRESH   0.5f
#define MAX_DET 100
#define CAP    1504        // max valid per class (<= NROI), padded
#define MASK_CAP 512       // bitmask NMS path supported up to this nv
#define RANK_CAP 512       // rank-sort path supported up to this nv
#define SEGCAP 1504        // per-class kept-entry capacity
#define SMEM_SC_CAP 4096   // kept-score smem buffer in k_final
#define CAND_CAP 2048      // level-0 candidate buffer in k_final
#define TMAIN  1024
#define TFIN   512
#define NWARP  (TMAIN/32)
#define NWFIN  (TFIN/32)

// Output float4 quads split across the NCLS blocks of k_main
#define QTOT   ((NTOT*8)/4)        // 240000
#define QPB    (QTOT/NCLS)         // 3000 per block

// ---------------- scratch (device globals; no allocation) ----------------
// g_segcnt[] is unconditionally (re)written by every k_main run (including
// nv==0 classes), and k_final only reads it after k_main completes -> no
// cross-replay reset is needed anywhere.
__device__ float g_segsc[NCLS*SEGCAP];     // kept scores, per-class segments
__device__ float g_seglist[NCLS*SEGCAP*8]; // kept entries {s, j, x1, y1}{x2, y2, 0, 0}
__device__ int   g_segcnt[NCLS];

__device__ __forceinline__ unsigned int mono_key(float s) {
    unsigned int b = __float_as_uint(s);
    return (b & 0x80000000u) ? ~b : (b | 0x80000000u);
}
__device__ __forceinline__ float inv_mono(unsigned int u) {
    unsigned int b = (u & 0x80000000u) ? (u & 0x7FFFFFFFu) : ~u;
    return __uint_as_float(b);
}

// ---------------- kernel 1: fill + per-class compact+sort+decode+NMS ----------------
struct SMem {
    unsigned long long skey[2048];
    float sx1[CAP], sy1[CAP], sx2[CAP], sy2[CAP], sar[CAP], ssc[CAP];
    unsigned long long smask[MASK_CAP*8];  // reused as sup[] bytes in fallback
    unsigned long long skeep[24];
    int   cnt;
    int   kcnt;
};

__global__ __launch_bounds__(TMAIN) void k_main(const float* __restrict__ rois,
                                                const float* __restrict__ delta,
                                                const float* __restrict__ prob,
                                                const float* __restrict__ iminfo,
                                                float* __restrict__ out) {
    extern __shared__ char smem_raw[];
    SMem& sm = *reinterpret_cast<SMem*>(smem_raw);
    const int c    = blockIdx.x;
    const int cls  = c + 1;
    const int tid  = threadIdx.x;
    const int lane = tid & 31;
    const int wid  = tid >> 5;
    const unsigned FULL = 0xFFFFFFFFu;

    if (tid == 0) { sm.cnt = 0; sm.kcnt = 0; }
    // init visibility enforced by the barrier below (after prefetch/fill)

    // ---- prefetch this thread's prob entries + iminfo (latency hides behind fill) ----
    const int NIT = (NROI + TMAIN - 1) / TMAIN;   // 2
    float sv[NIT];
    #pragma unroll
    for (int it = 0; it < NIT; ++it) {
        int j = tid + it*TMAIN;
        sv[it] = (j < NROI) ? prob[(size_t)j*81 + cls] : 0.0f;
    }
    const float H = iminfo[0], W = iminfo[1];

    // ---- fill this block's 1/NCLS slice of the output ----
    // layout (float32): dets[NTOT*6]=0 | cls_idx[NTOT]=class | keep[NTOT]=0
    {
        float4* o4 = reinterpret_cast<float4*>(out);
        const int q0 = c*QPB, q1 = q0 + QPB;
        for (int q = q0 + tid; q < q1; q += TMAIN) {
            float4 v = make_float4(0.f,0.f,0.f,0.f);
            if (q >= (NTOT*6)/4 && q < (NTOT*7)/4) {
                int r0 = q*4 - NTOT*6;
                v.x = (float)((r0+0)/NROI + 1);
                v.y = (float)((r0+1)/NROI + 1);
                v.z = (float)((r0+2)/NROI + 1);
                v.w = (float)((r0+3)/NROI + 1);
            }
            o4[q] = v;
        }
    }
    __syncthreads();   // orders sm.cnt/kcnt=0 before the atomics below

    // ---- compact valid entries (warp-aggregated shared atomic) ----
    #pragma unroll
    for (int it = 0; it < NIT; ++it) {
        int j = tid + it*TMAIN;
        bool valid = (j < NROI) && (sv[it] > SCORE_THRESH);
        unsigned m = __ballot_sync(FULL, valid);
        int base = 0;
        if (lane == 0 && m) base = atomicAdd(&sm.cnt, __popc(m));
        base = __shfl_sync(FULL, base, 0);
        if (valid) {
            int p = base + __popc(m & ((1u << lane) - 1u));
            sm.skey[p] = ((unsigned long long)mono_key(sv[it]) << 32)
                       | (unsigned long long)(0xFFFFFFFFu - (unsigned)j);
        }
    }
    __syncthreads();
    const int nv = sm.cnt;
    if (nv == 0) {
        if (tid == 0) g_segcnt[c] = 0;   // must be written every run
        return;
    }

    const float lx = W - 1.0f, ly = H - 1.0f;

    if (nv <= RANK_CAP) {
        // ---- rank sort + decode fused; global loads hoisted above rank loop ----
        for (int j = tid; j < nv; j += TMAIN) {
            unsigned long long k = sm.skey[j];
            int idx = (int)(0xFFFFFFFFu - (unsigned int)(k & 0xFFFFFFFFull));
            float s = inv_mono((unsigned int)(k >> 32));

            // issue global loads now; latency hides behind the rank loop below
            float rx1 = rois[idx*5+1], ry1 = rois[idx*5+2];
            float rx2 = rois[idx*5+3], ry2 = rois[idx*5+4];
            const float4 d4 = *reinterpret_cast<const float4*>(delta + (size_t)idx*(4*81) + 4*cls);

            int r = 0;
            int i = 0;
            for (; i + 4 <= nv; i += 4) {               // unrolled rank count
                r += (sm.skey[i]   > k);
                r += (sm.skey[i+1] > k);
                r += (sm.skey[i+2] > k);
                r += (sm.skey[i+3] > k);
            }
            for (; i < nv; i++) r += (sm.skey[i] > k);  // keys unique

            float w  = rx2 - rx1 + 1.0f;
            float h  = ry2 - ry1 + 1.0f;
            float cx = rx1 + 0.5f*w;
            float cy = ry1 + 0.5f*h;
            float dx = d4.x / 10.0f, dy = d4.y / 10.0f;
            float dw = d4.z / 5.0f,  dh = d4.w / 5.0f;
            float pcx = cx + w*dx;
            float pcy = cy + h*dy;
            float pw  = w * expf(dw);
            float ph  = h * expf(dh);
            float bx1 = fminf(fmaxf(pcx - 0.5f*pw,        0.0f), lx);
            float by1 = fminf(fmaxf(pcy - 0.5f*ph,        0.0f), ly);
            float bx2 = fminf(fmaxf(pcx + 0.5f*pw - 1.0f, 0.0f), lx);
            float by2 = fminf(fmaxf(pcy + 0.5f*ph - 1.0f, 0.0f), ly);

            sm.sx1[r] = bx1; sm.sy1[r] = by1; sm.sx2[r] = bx2; sm.sy2[r] = by2;
            sm.sar[r] = (bx2 - bx1 + 1.0f) * (by2 - by1 + 1.0f);
            sm.ssc[r] = s;
        }
        __syncthreads();
    } else {
        // ---- fallback: bitonic sort over m = next pow2 >= nv ----
        int m = 1; while (m < nv) m <<= 1;
        for (int j = nv + tid; j < m; j += TMAIN) sm.skey[j] = 0ull; // pads last
        __syncthreads();
        for (int size = 2; size <= m; size <<= 1) {
            for (int stride = size >> 1; stride > 0; stride >>= 1) {
                for (int t = tid; t < (m >> 1); t += TMAIN) {
                    int pos = 2*t - (t & (stride - 1));
                    bool desc = (pos & size) == 0;
                    unsigned long long a = sm.skey[pos], b = sm.skey[pos + stride];
                    if ((a < b) == desc) { sm.skey[pos] = b; sm.skey[pos + stride] = a; }
                }
                __syncthreads();
            }
        }
        for (int j = tid; j < nv; j += TMAIN) {
            unsigned long long k = sm.skey[j];
            int idx = (int)(0xFFFFFFFFu - (unsigned int)(k & 0xFFFFFFFFull));
            float s = inv_mono((unsigned int)(k >> 32));
            float rx1 = rois[idx*5+1], ry1 = rois[idx*5+2];
            float rx2 = rois[idx*5+3], ry2 = rois[idx*5+4];
            const float4 d4 = *reinterpret_cast<const float4*>(delta + (size_t)idx*(4*81) + 4*cls);
            float w  = rx2 - rx1 + 1.0f;
            float h  = ry2 - ry1 + 1.0f;
            float cx = rx1 + 0.5f*w;
            float cy = ry1 + 0.5f*h;
            float dx = d4.x / 10.0f, dy = d4.y / 10.0f;
            float dw = d4.z / 5.0f,  dh = d4.w / 5.0f;
            float pcx = cx + w*dx;
            float pcy = cy + h*dy;
            float pw  = w * expf(dw);
            float ph  = h * expf(dh);
            float bx1 = fminf(fmaxf(pcx - 0.5f*pw,        0.0f), lx);
            float by1 = fminf(fmaxf(pcy - 0.5f*ph,        0.0f), ly);
            float bx2 = fminf(fmaxf(pcx + 0.5f*pw - 1.0f, 0.0f), lx);
            float by2 = fminf(fmaxf(pcy + 0.5f*ph - 1.0f, 0.0f), ly);
            sm.sx1[j] = bx1; sm.sy1[j] = by1; sm.sx2[j] = bx2; sm.sy2[j] = by2;
            sm.sar[j] = (bx2 - bx1 + 1.0f) * (by2 - by1 + 1.0f);
            sm.ssc[j] = s;
        }
        __syncthreads();
    }

    // ---- NMS ----
    if (nv <= MASK_CAP) {
        // warp-per-row ballot mask build: lanes cover 64-bit word chunks
        const int MW = (nv + 63) >> 6;
        for (int i = wid; i < nv; i += NWARP) {
            float x1 = sm.sx1[i], y1 = sm.sy1[i], x2 = sm.sx2[i], y2 = sm.sy2[i];
            float ai = sm.sar[i];
            for (int ww = (i >> 6); ww < MW; ww++) {
                int j1 = ww*64 + lane;
                int j2 = j1 + 32;
                bool p1 = false, p2 = false;
                if (j1 > i && j1 < nv) {
                    float iw = fminf(x2, sm.sx2[j1]) - fmaxf(x1, sm.sx1[j1]) + 1.0f;
                    float ih = fminf(y2, sm.sy2[j1]) - fmaxf(y1, sm.sy1[j1]) + 1.0f;
                    iw = fmaxf(iw, 0.0f); ih = fmaxf(ih, 0.0f);
                    float inter = iw * ih;
                    p1 = (inter / (ai + sm.sar[j1] - inter)) > NMS_THRESH;
                }
                if (j2 > i && j2 < nv) {
                    float iw = fminf(x2, sm.sx2[j2]) - fmaxf(x1, sm.sx1[j2]) + 1.0f;
                    float ih = fminf(y2, sm.sy2[j2]) - fmaxf(y1, sm.sy1[j2]) + 1.0f;
                    iw = fmaxf(iw, 0.0f); ih = fmaxf(ih, 0.0f);
                    float inter = iw * ih;
                    p2 = (inter / (ai + sm.sar[j2] - inter)) > NMS_THRESH;
                }
                unsigned lo = __ballot_sync(FULL, p1);
                unsigned hi = __ballot_sync(FULL, p2);
                if (lane == 0)
                    sm.smask[i*8 + ww] = (unsigned long long)lo
                                       | ((unsigned long long)hi << 32);
            }
        }
        __syncthreads();
        if (tid == 0) {
            if (MW <= 2) {
                // scalar-register scan with depth-2 LDS prefetch: no local memory,
                // per-iteration chain is pure ALU.
                unsigned long long sup0 = 0ull, sup1 = 0ull;
                unsigned long long keep0 = 0ull, keep1 = 0ull;
                const int lim0 = (nv < 64) ? nv : 64;
                unsigned long long a0 = sm.smask[0], a1 = (MW > 1) ? sm.smask[1] : 0ull;
                unsigned long long b0 = 0ull, b1 = 0ull;
                if (nv > 1) { b0 = sm.smask[8]; b1 = (MW > 1) ? sm.smask[9] : 0ull; }
                for (int i = 0; i < lim0; i++) {
                    unsigned long long c0 = a0, c1 = a1;
                    a0 = b0; a1 = b1;
                    if (i + 2 < nv) {
                        int base = (i + 2)*8;
                        b0 = sm.smask[base];
                        b1 = (MW > 1) ? sm.smask[base + 1] : 0ull;
                    }
                    if (!((sup0 >> i) & 1ull)) {
                        keep0 |= 1ull << i;
                        sup0 |= c0;
                        sup1 |= c1;
                    }
                }
                if (nv > 64) {
                    unsigned long long a = sm.smask[64*8 + 1];
                    unsigned long long b = (nv > 65) ? sm.smask[65*8 + 1] : 0ull;
                    for (int i = 64; i < nv; i++) {
                        unsigned long long cc = a;
                        a = b;
                        if (i + 2 < nv) b = sm.smask[(i + 2)*8 + 1];
                        int bpos = i - 64;
                        if (!((sup1 >> bpos) & 1ull)) {
                            keep1 |= 1ull << bpos;
                            sup1 |= cc;
                        }
                    }
                }
                sm.skeep[0] = keep0;
                if (MW > 1) sm.skeep[1] = keep1;
            } else {
                unsigned long long keepw[8], supw[8];
                #pragma unroll
                for (int w = 0; w < 8; w++) { keepw[w] = 0ull; supw[w] = 0ull; }
                for (int i = 0; i < nv; i++) {
                    if (!((supw[i >> 6] >> (i & 63)) & 1ull)) {
                        keepw[i >> 6] |= (1ull << (i & 63));
                        for (int w = (i >> 6); w < MW; w++) supw[w] |= sm.smask[i*8 + w];
                    }
                }
                for (int w = 0; w < MW; w++) sm.skeep[w] = keepw[w];
            }
        }
        __syncthreads();
    } else {
        unsigned char* sup = reinterpret_cast<unsigned char*>(sm.smask);
        for (int j = tid; j < nv; j += TMAIN) sup[j] = 0;
        if (tid < 24) sm.skeep[tid] = 0ull;
        __syncthreads();
        int i = 0;
        while (i < nv) {
            if (tid == 0) sm.skeep[i >> 6] |= (1ull << (i & 63));
            float x1 = sm.sx1[i], y1 = sm.sy1[i], x2 = sm.sx2[i], y2 = sm.sy2[i];
            float ai = sm.sar[i];
            for (int j = i + 1 + tid; j < nv; j += TMAIN) {
                if (sup[j]) continue;
                float iw = fminf(x2, sm.sx2[j]) - fmaxf(x1, sm.sx1[j]) + 1.0f;
                float ih = fminf(y2, sm.sy2[j]) - fmaxf(y1, sm.sy1[j]) + 1.0f;
                iw = fmaxf(iw, 0.0f);
                ih = fmaxf(ih, 0.0f);
                float inter = iw * ih;
                float iou = inter / (ai + sm.sar[j] - inter);
                if (iou > NMS_THRESH) sup[j] = 1;
            }
            __syncthreads();
            ++i;
            while (i < nv && sup[i]) ++i;
        }
    }

    // ---- append kept entries to this class's PRIVATE segment (shared atomic only) ----
    const int AIT = (nv + TMAIN - 1) / TMAIN;
    for (int it = 0; it < AIT; ++it) {
        int j = tid + it*TMAIN;
        bool kp = (j < nv) && ((sm.skeep[j >> 6] >> (j & 63)) & 1ull);
        unsigned m = __ballot_sync(FULL, kp);
        int base = 0;
        if (lane == 0 && m) base = atomicAdd(&sm.kcnt, __popc(m));
        base = __shfl_sync(FULL, base, 0);
        if (kp) {
            int p = base + __popc(m & ((1u << lane) - 1u));
            g_segsc[c*SEGCAP + p] = sm.ssc[j];
            float4* L = reinterpret_cast<float4*>(g_seglist + (size_t)(c*SEGCAP + p)*8);
            L[0] = make_float4(sm.ssc[j], (float)j, sm.sx1[j], sm.sy1[j]);
            L[1] = make_float4(sm.sx2[j], sm.sy2[j], 0.f, 0.f);
        }
    }
    __syncthreads();
    if (tid == 0) g_segcnt[c] = sm.kcnt;   // written every run
}

// ---------------- kernel 2: smem radix-select kth + scatter ----------------
__global__ __launch_bounds__(TFIN) void k_final(float* __restrict__ out) {
    const int tid = threadIdx.x;
    const int lane = tid & 31, w = tid >> 5;
    const unsigned FULL = 0xFFFFFFFFu;

    __shared__ float ssc[SMEM_SC_CAP];
    __shared__ unsigned int cand[CAND_CAP];
    __shared__ int offs[NCLS+1];
    __shared__ int hist[256];
    __shared__ int wtot[8];
    __shared__ unsigned int s_prefix;
    __shared__ int s_need;
    __shared__ int s_ncand;
    __shared__ int s_cc;

    // PDL: launched before k_main finished; wait before consuming its output.
    cudaGridDependencySynchronize();

    // per-class counts -> offsets
    if (tid < NCLS) offs[tid + 1] = g_segcnt[tid];
    if (tid == TFIN-1) { s_prefix = 0u; s_need = MAX_DET; s_cc = 0; s_ncand = 0; }
    __syncthreads();
    if (tid == 0) {
        offs[0] = 0;
        for (int k = 1; k <= NCLS; k++) offs[k] += offs[k-1];
    }
    __syncthreads();
    const int count = offs[NCLS];

    int   filt = 0;
    float kth  = -CUDART_INF_F;

    if (count > MAX_DET) {
        const bool smem_path = (count <= SMEM_SC_CAP);
        if (tid < 256) hist[tid] = 0;
        __syncthreads();

        // fused pass: gather scores to dense smem AND build the level-0 histogram
        for (int cc = w; cc < NCLS; cc += NWFIN) {
            int off = offs[cc], n = offs[cc+1] - off;
            for (int k = lane; k < n; k += 32) {
                float v = g_segsc[cc*SEGCAP + k];
                if (smem_path) ssc[off + k] = v;
                atomicAdd(&hist[mono_key(v) >> 24], 1);
            }
        }
        __syncthreads();

        // ---- level 0 select (records the chosen bin's population) ----
        {
            const int need = s_need;
            int h = (tid < 256) ? hist[tid] : 0;
            int v = h;
            #pragma unroll
            for (int off = 1; off < 32; off <<= 1) {
                int u2 = __shfl_down_sync(FULL, v, off);
                if (lane + off < 32) v += u2;
            }
            if (lane == 0 && w < 8) wtot[w] = v;
            __syncthreads();
            if (tid < 256) {
                int add = 0;
                #pragma unroll
                for (int k = 0; k < 8; k++) if (k > w) add += wtot[k];
                int sfx = v + add;
                int hi  = sfx - h;
                if (sfx >= need && hi < need) {
                    s_prefix = (unsigned int)tid << 24;
                    s_need   = need - hi;
                    s_ncand  = h;                 // elements sharing the chosen top-8 prefix
                }
            }
            __syncthreads();
        }

        const int ncand = s_ncand;
        const unsigned int topbin = s_prefix >> 24;
        if (ncand <= CAND_CAP) {
            // ---- compact the candidates (ballot-aggregated) ----
            if (smem_path) {
                for (int j0 = 0; j0 < count; j0 += TFIN) {
                    int j = j0 + tid;
                    unsigned int u = 0;
                    bool hit = false;
                    if (j < count) {
                        u = mono_key(ssc[j]);
                        hit = (u >> 24) == topbin;
                    }
                    unsigned m = __ballot_sync(FULL, hit);
                    int base = 0;
                    if (lane == 0 && m) base = atomicAdd(&s_cc, __popc(m));
                    base = __shfl_sync(FULL, base, 0);
                    if (hit) cand[base + __popc(m & ((1u << lane) - 1u))] = u;
                }
            } else {
                for (int cc = w; cc < NCLS; cc += NWFIN) {
                    int n = offs[cc+1] - offs[cc];
                    for (int k0 = 0; k0 < n; k0 += 32) {
                        int k = k0 + lane;
                        unsigned int u = 0;
                        bool hit = false;
                        if (k < n) {
                            u = mono_key(g_segsc[cc*SEGCAP + k]);
                            hit = (u >> 24) == topbin;
                        }
                        unsigned m = __ballot_sync(FULL, hit);
                        int base = 0;
                        if (lane == 0 && m) base = atomicAdd(&s_cc, __popc(m));
                        base = __shfl_sync(FULL, base, 0);
                        if (hit) cand[base + __popc(m & ((1u << lane) - 1u))] = u;
                    }
                }
            }
            __syncthreads();

            // ---- levels 1..3 over the small candidate set ----
            #pragma unroll
            for (int level = 1; level < 4; ++level) {
                const int shift = 24 - 8*level;
                const unsigned int dmask = 0xFFFFFFFFu << (shift + 8);
                if (tid < 256) hist[tid] = 0;
                __syncthreads();
                const unsigned int pfx = s_prefix;
                for (int j = tid; j < ncand; j += TFIN) {
                    unsigned int u = cand[j];
                    if ((u & dmask) == pfx)
                        atomicAdd(&hist[(u >> shift) & 0xFFu], 1);
                }
                __syncthreads();
                const int need = s_need;
                int h = (tid < 256) ? hist[tid] : 0;
                int v = h;
                #pragma unroll
                for (int off = 1; off < 32; off <<= 1) {
                    int u2 = __shfl_down_sync(FULL, v, off);
                    if (lane + off < 32) v += u2;
                }
                if (lane == 0 && w < 8) wtot[w] = v;
                __syncthreads();
                if (tid < 256) {
                    int add = 0;
                    #pragma unroll
                    for (int k = 0; k < 8; k++) if (k > w) add += wtot[k];
                    int sfx = v + add;
                    int hi  = sfx - h;
                    if (sfx >= need && hi < need) {
                        s_prefix = pfx | ((unsigned int)tid << shift);
                        s_need   = need - hi;
                    }
                }
                __syncthreads();
            }
        } else {
            // fallback: full scans (pathological tie mass in one bin)
            #pragma unroll
            for (int level = 1; level < 4; ++level) {
                const int shift = 24 - 8*level;
                const unsigned int dmask = 0xFFFFFFFFu << (shift + 8);
                if (tid < 256) hist[tid] = 0;
                __syncthreads();
                const unsigned int pfx = s_prefix;
                if (smem_path) {
                    for (int j = tid; j < count; j += TFIN) {
                        unsigned int u = mono_key(ssc[j]);
                        if ((u & dmask) == pfx)
                            atomicAdd(&hist[(u >> shift) & 0xFFu], 1);
                    }
                } else {
                    for (int cc = w; cc < NCLS; cc += NWFIN) {
                        int n = offs[cc+1] - offs[cc];
                        for (int k = lane; k < n; k += 32) {
                            unsigned int u = mono_key(g_segsc[cc*SEGCAP + k]);
                            if ((u & dmask) == pfx)
                                atomicAdd(&hist[(u >> shift) & 0xFFu], 1);
                        }
                    }
                }
                __syncthreads();
                const int need = s_need;
                int h = (tid < 256) ? hist[tid] : 0;
                int v = h;
                #pragma unroll
                for (int off = 1; off < 32; off <<= 1) {
                    int u2 = __shfl_down_sync(FULL, v, off);
                    if (lane + off < 32) v += u2;
                }
                if (lane == 0 && w < 8) wtot[w] = v;
                __syncthreads();
                if (tid < 256) {
                    int add = 0;
                    #pragma unroll
                    for (int k = 0; k < 8; k++) if (k > w) add += wtot[k];
                    int sfx = v + add;
                    int hi  = sfx - h;
                    if (sfx >= need && hi < need) {
                        s_prefix = pfx | ((unsigned int)tid << shift);
                        s_need   = need - hi;
                    }
                }
                __syncthreads();
            }
        }
        filt = 1;
        kth  = inv_mono(s_prefix);        // exact value of the MAX_DET-th largest
    }

    // ---- scatter kept rows from segments into the output ----
    for (int cc = w; cc < NCLS; cc += NWFIN) {
        int n = offs[cc+1] - offs[cc];
        for (int k = lane; k < n; k += 32) {
            const float4 L0 = reinterpret_cast<const float4*>(g_seglist + (size_t)(cc*SEGCAP + k)*8)[0];
            float s = L0.x;
            if (filt && !(s >= kth)) continue;
            const float4 L1 = reinterpret_cast<const float4*>(g_seglist + (size_t)(cc*SEGCAP + k)*8)[1];
            int j = (int)L0.y;
            int r = cc*NROI + j;
            float* d = out + (size_t)r*6;
            d[0] = 0.0f;
            d[1] = L0.z;  // x1
            d[2] = L0.w;  // y1
            d[3] = L1.x;  // x2
            d[4] = L1.y;  // y2
            d[5] = s;
            out[NTOT*7 + r] = 1.0f;   // keep flag
        }
    }
    // no reset needed: g_segcnt is rewritten by every k_main run
}

extern "C" void kernel_launch(void* const* d_in, const int* in_sizes, int n_in,
                              void* d_out, int out_size) {
    const float* rois   = (const float*)d_in[0];
    const float* delta  = (const float*)d_in[1];
    const float* prob   = (const float*)d_in[2];
    const float* iminfo = (const float*)d_in[3];
    float* out = (float*)d_out;

    static_assert(sizeof(SMem) < 100*1024, "smem budget");
    cudaFuncSetAttribute(k_main, cudaFuncAttributeMaxDynamicSharedMemorySize,
                         (int)sizeof(SMem));

    k_main<<<NCLS, TMAIN, sizeof(SMem)>>>(rois, delta, prob, iminfo, out);

    // k_final with programmatic dependent launch: its launch/prologue overlaps
    // k_main's tail; device-side cudaGridDependencySynchronize() provides the
    // ordering before it reads k_main's results.
    cudaLaunchConfig_t cfg = {};
    cfg.gridDim  = dim3(1, 1, 1);
    cfg.blockDim = dim3(TFIN, 1, 1);
    cfg.dynamicSmemBytes = 0;
    cfg.stream = 0;
    cudaLaunchAttribute attrs[1];
    attrs[0].id = cudaLaunchAttributeProgrammaticStreamSerialization;
    attrs[0].val.programmaticStreamSerializationAllowed = 1;
    cfg.attrs = attrs;
    cfg.numAttrs = 1;
    cudaLaunchKernelEx(&cfg, k_final, out);
}

// round 15
// speedup vs baseline: 1.1631x; 1.1631x over previous
#include <cuda_runtime.h>
#include <math_constants.h>

#define NROI   1500
#define NCLS   80          // foreground classes 1..80
#define NTOT   (NROI*NCLS) // 120000
#define SCORE_THRESH 0.05f
#define NMS_THRESH   0.5f
#define MAX_DET 100
#define CAP    1504        // max valid per class (<= NROI), padded
#define MASK_CAP 512       // bitmask NMS path supported up to this nv
#define RANK_CAP 512       // rank-sort path supported up to this nv
#define SMEM_SC_CAP 4096   // kept-score smem buffer in k_final
#define CAND_CAP 2048      // level-0 candidate buffer in k_final
#define TMAIN  1024
#define TFIN   1024
#define NWARP  (TMAIN/32)

// Output float4 quads split across the NCLS blocks of k_main
#define QTOT   ((NTOT*8)/4)        // 240000
#define QPB    (QTOT/NCLS)         // 3000 per block

// ---------------- scratch (device globals; no allocation) ----------------
// g_kcount is zero-initialized at load and restored to 0 at the end of every
// k_final run -> every invocation (correctness, capture, replays) sees 0.
__device__ float g_list[NTOT*8];   // kept entries: {s, c, j, x1}{y1, x2, y2, 0}
__device__ int   g_kcount;

__device__ __forceinline__ unsigned int mono_key(float s) {
    unsigned int b = __float_as_uint(s);
    return (b & 0x80000000u) ? ~b : (b | 0x80000000u);
}
__device__ __forceinline__ float inv_mono(unsigned int u) {
    unsigned int b = (u & 0x80000000u) ? (u & 0x7FFFFFFFu) : ~u;
    return __uint_as_float(b);
}

// ---------------- kernel 1: fill + per-class compact+sort+decode+NMS ----------------
struct SMem {
    unsigned long long skey[2048];
    float sx1[CAP], sy1[CAP], sx2[CAP], sy2[CAP], sar[CAP], ssc[CAP];
    unsigned long long smask[MASK_CAP*8];  // reused as sup[] bytes in fallback
    unsigned long long skeep[24];
    int   cnt;
};

__global__ __launch_bounds__(TMAIN) void k_main(const float* __restrict__ rois,
                                                const float* __restrict__ delta,
                                                const float* __restrict__ prob,
                                                const float* __restrict__ iminfo,
                                                float* __restrict__ out) {
    extern __shared__ char smem_raw[];
    SMem& sm = *reinterpret_cast<SMem*>(smem_raw);
    const int c    = blockIdx.x;
    const int cls  = c + 1;
    const int tid  = threadIdx.x;
    const int lane = tid & 31;
    const int wid  = tid >> 5;
    const unsigned FULL = 0xFFFFFFFFu;

    if (tid == 0) sm.cnt = 0;
    // init visibility enforced by the barrier below (after prefetch/fill)

    // ---- prefetch this thread's prob entries + iminfo (latency hides behind fill) ----
    const int NIT = (NROI + TMAIN - 1) / TMAIN;   // 2
    float sv[NIT];
    #pragma unroll
    for (int it = 0; it < NIT; ++it) {
        int j = tid + it*TMAIN;
        sv[it] = (j < NROI) ? prob[(size_t)j*81 + cls] : 0.0f;
    }
    const float H = iminfo[0], W = iminfo[1];

    // ---- fill this block's 1/NCLS slice of the output ----
    // layout (float32): dets[NTOT*6]=0 | cls_idx[NTOT]=class | keep[NTOT]=0
    {
        float4* o4 = reinterpret_cast<float4*>(out);
        const int q0 = c*QPB, q1 = q0 + QPB;
        for (int q = q0 + tid; q < q1; q += TMAIN) {
            float4 v = make_float4(0.f,0.f,0.f,0.f);
            if (q >= (NTOT*6)/4 && q < (NTOT*7)/4) {
                int r0 = q*4 - NTOT*6;
                v.x = (float)((r0+0)/NROI + 1);
                v.y = (float)((r0+1)/NROI + 1);
                v.z = (float)((r0+2)/NROI + 1);
                v.w = (float)((r0+3)/NROI + 1);
            }
            o4[q] = v;
        }
    }
    __syncthreads();   // orders sm.cnt=0 before the atomics below

    // ---- compact valid entries (warp-aggregated shared atomic) ----
    #pragma unroll
    for (int it = 0; it < NIT; ++it) {
        int j = tid + it*TMAIN;
        bool valid = (j < NROI) && (sv[it] > SCORE_THRESH);
        unsigned m = __ballot_sync(FULL, valid);
        int base = 0;
        if (lane == 0 && m) base = atomicAdd(&sm.cnt, __popc(m));
        base = __shfl_sync(FULL, base, 0);
        if (valid) {
            int p = base + __popc(m & ((1u << lane) - 1u));
            sm.skey[p] = ((unsigned long long)mono_key(sv[it]) << 32)
                       | (unsigned long long)(0xFFFFFFFFu - (unsigned)j);
        }
    }
    __syncthreads();
    const int nv = sm.cnt;
    if (nv == 0) return;

    const float lx = W - 1.0f, ly = H - 1.0f;

    if (nv <= RANK_CAP) {
        // ---- rank sort + decode fused; global loads hoisted above rank loop ----
        for (int j = tid; j < nv; j += TMAIN) {
            unsigned long long k = sm.skey[j];
            int idx = (int)(0xFFFFFFFFu - (unsigned int)(k & 0xFFFFFFFFull));
            float s = inv_mono((unsigned int)(k >> 32));

            // issue global loads now; latency hides behind the rank loop below
            float rx1 = rois[idx*5+1], ry1 = rois[idx*5+2];
            float rx2 = rois[idx*5+3], ry2 = rois[idx*5+4];
            const float4 d4 = *reinterpret_cast<const float4*>(delta + (size_t)idx*(4*81) + 4*cls);

            int r = 0;
            int i = 0;
            for (; i + 4 <= nv; i += 4) {               // unrolled rank count
                r += (sm.skey[i]   > k);
                r += (sm.skey[i+1] > k);
                r += (sm.skey[i+2] > k);
                r += (sm.skey[i+3] > k);
            }
            for (; i < nv; i++) r += (sm.skey[i] > k);  // keys unique

            float w  = rx2 - rx1 + 1.0f;
            float h  = ry2 - ry1 + 1.0f;
            float cx = rx1 + 0.5f*w;
            float cy = ry1 + 0.5f*h;
            float dx = d4.x / 10.0f, dy = d4.y / 10.0f;
            float dw = d4.z / 5.0f,  dh = d4.w / 5.0f;
            float pcx = cx + w*dx;
            float pcy = cy + h*dy;
            float pw  = w * expf(dw);
            float ph  = h * expf(dh);
            float bx1 = fminf(fmaxf(pcx - 0.5f*pw,        0.0f), lx);
            float by1 = fminf(fmaxf(pcy - 0.5f*ph,        0.0f), ly);
            float bx2 = fminf(fmaxf(pcx + 0.5f*pw - 1.0f, 0.0f), lx);
            float by2 = fminf(fmaxf(pcy + 0.5f*ph - 1.0f, 0.0f), ly);

            sm.sx1[r] = bx1; sm.sy1[r] = by1; sm.sx2[r] = bx2; sm.sy2[r] = by2;
            sm.sar[r] = (bx2 - bx1 + 1.0f) * (by2 - by1 + 1.0f);
            sm.ssc[r] = s;
        }
        __syncthreads();
    } else {
        // ---- fallback: bitonic sort over m = next pow2 >= nv ----
        int m = 1; while (m < nv) m <<= 1;
        for (int j = nv + tid; j < m; j += TMAIN) sm.skey[j] = 0ull; // pads last
        __syncthreads();
        for (int size = 2; size <= m; size <<= 1) {
            for (int stride = size >> 1; stride > 0; stride >>= 1) {
                for (int t = tid; t < (m >> 1); t += TMAIN) {
                    int pos = 2*t - (t & (stride - 1));
                    bool desc = (pos & size) == 0;
                    unsigned long long a = sm.skey[pos], b = sm.skey[pos + stride];
                    if ((a < b) == desc) { sm.skey[pos] = b; sm.skey[pos + stride] = a; }
                }
                __syncthreads();
            }
        }
        for (int j = tid; j < nv; j += TMAIN) {
            unsigned long long k = sm.skey[j];
            int idx = (int)(0xFFFFFFFFu - (unsigned int)(k & 0xFFFFFFFFull));
            float s = inv_mono((unsigned int)(k >> 32));
            float rx1 = rois[idx*5+1], ry1 = rois[idx*5+2];
            float rx2 = rois[idx*5+3], ry2 = rois[idx*5+4];
            const float4 d4 = *reinterpret_cast<const float4*>(delta + (size_t)idx*(4*81) + 4*cls);
            float w  = rx2 - rx1 + 1.0f;
            float h  = ry2 - ry1 + 1.0f;
            float cx = rx1 + 0.5f*w;
            float cy = ry1 + 0.5f*h;
            float dx = d4.x / 10.0f, dy = d4.y / 10.0f;
            float dw = d4.z / 5.0f,  dh = d4.w / 5.0f;
            float pcx = cx + w*dx;
            float pcy = cy + h*dy;
            float pw  = w * expf(dw);
            float ph  = h * expf(dh);
            float bx1 = fminf(fmaxf(pcx - 0.5f*pw,        0.0f), lx);
            float by1 = fminf(fmaxf(pcy - 0.5f*ph,        0.0f), ly);
            float bx2 = fminf(fmaxf(pcx + 0.5f*pw - 1.0f, 0.0f), lx);
            float by2 = fminf(fmaxf(pcy + 0.5f*ph - 1.0f, 0.0f), ly);
            sm.sx1[j] = bx1; sm.sy1[j] = by1; sm.sx2[j] = bx2; sm.sy2[j] = by2;
            sm.sar[j] = (bx2 - bx1 + 1.0f) * (by2 - by1 + 1.0f);
            sm.ssc[j] = s;
        }
        __syncthreads();
    }

    // ---- NMS ----
    if (nv <= MASK_CAP) {
        // warp-per-row ballot mask build: lanes cover 64-bit word chunks
        const int MW = (nv + 63) >> 6;
        for (int i = wid; i < nv; i += NWARP) {
            float x1 = sm.sx1[i], y1 = sm.sy1[i], x2 = sm.sx2[i], y2 = sm.sy2[i];
            float ai = sm.sar[i];
            for (int ww = (i >> 6); ww < MW; ww++) {
                int j1 = ww*64 + lane;
                int j2 = j1 + 32;
                bool p1 = false, p2 = false;
                if (j1 > i && j1 < nv) {
                    float iw = fminf(x2, sm.sx2[j1]) - fmaxf(x1, sm.sx1[j1]) + 1.0f;
                    float ih = fminf(y2, sm.sy2[j1]) - fmaxf(y1, sm.sy1[j1]) + 1.0f;
                    iw = fmaxf(iw, 0.0f); ih = fmaxf(ih, 0.0f);
                    float inter = iw * ih;
                    p1 = (inter / (ai + sm.sar[j1] - inter)) > NMS_THRESH;
                }
                if (j2 > i && j2 < nv) {
                    float iw = fminf(x2, sm.sx2[j2]) - fmaxf(x1, sm.sx1[j2]) + 1.0f;
                    float ih = fminf(y2, sm.sy2[j2]) - fmaxf(y1, sm.sy1[j2]) + 1.0f;
                    iw = fmaxf(iw, 0.0f); ih = fmaxf(ih, 0.0f);
                    float inter = iw * ih;
                    p2 = (inter / (ai + sm.sar[j2] - inter)) > NMS_THRESH;
                }
                unsigned lo = __ballot_sync(FULL, p1);
                unsigned hi = __ballot_sync(FULL, p2);
                if (lane == 0)
                    sm.smask[i*8 + ww] = (unsigned long long)lo
                                       | ((unsigned long long)hi << 32);
            }
        }
        __syncthreads();
        if (tid == 0) {
            if (MW <= 2) {
                // scalar-register scan with depth-2 LDS prefetch: no local memory,
                // per-iteration chain is pure ALU.
                unsigned long long sup0 = 0ull, sup1 = 0ull;
                unsigned long long keep0 = 0ull, keep1 = 0ull;
                const int lim0 = (nv < 64) ? nv : 64;
                unsigned long long a0 = sm.smask[0], a1 = (MW > 1) ? sm.smask[1] : 0ull;
                unsigned long long b0 = 0ull, b1 = 0ull;
                if (nv > 1) { b0 = sm.smask[8]; b1 = (MW > 1) ? sm.smask[9] : 0ull; }
                for (int i = 0; i < lim0; i++) {
                    unsigned long long c0 = a0, c1 = a1;
                    a0 = b0; a1 = b1;
                    if (i + 2 < nv) {
                        int base = (i + 2)*8;
                        b0 = sm.smask[base];
                        b1 = (MW > 1) ? sm.smask[base + 1] : 0ull;
                    }
                    if (!((sup0 >> i) & 1ull)) {
                        keep0 |= 1ull << i;
                        sup0 |= c0;
                        sup1 |= c1;
                    }
                }
                if (nv > 64) {
                    unsigned long long a = sm.smask[64*8 + 1];
                    unsigned long long b = (nv > 65) ? sm.smask[65*8 + 1] : 0ull;
                    for (int i = 64; i < nv; i++) {
                        unsigned long long cc = a;
                        a = b;
                        if (i + 2 < nv) b = sm.smask[(i + 2)*8 + 1];
                        int bpos = i - 64;
                        if (!((sup1 >> bpos) & 1ull)) {
                            keep1 |= 1ull << bpos;
                            sup1 |= cc;
                        }
                    }
                }
                sm.skeep[0] = keep0;
                if (MW > 1) sm.skeep[1] = keep1;
            } else {
                unsigned long long keepw[8], supw[8];
                #pragma unroll
                for (int w = 0; w < 8; w++) { keepw[w] = 0ull; supw[w] = 0ull; }
                for (int i = 0; i < nv; i++) {
                    if (!((supw[i >> 6] >> (i & 63)) & 1ull)) {
                        keepw[i >> 6] |= (1ull << (i & 63));
                        for (int w = (i >> 6); w < MW; w++) supw[w] |= sm.smask[i*8 + w];
                    }
                }
                for (int w = 0; w < MW; w++) sm.skeep[w] = keepw[w];
            }
        }
        __syncthreads();
    } else {
        unsigned char* sup = reinterpret_cast<unsigned char*>(sm.smask);
        for (int j = tid; j < nv; j += TMAIN) sup[j] = 0;
        if (tid < 24) sm.skeep[tid] = 0ull;
        __syncthreads();
        int i = 0;
        while (i < nv) {
            if (tid == 0) sm.skeep[i >> 6] |= (1ull << (i & 63));
            float x1 = sm.sx1[i], y1 = sm.sy1[i], x2 = sm.sx2[i], y2 = sm.sy2[i];
            float ai = sm.sar[i];
            for (int j = i + 1 + tid; j < nv; j += TMAIN) {
                if (sup[j]) continue;
                float iw = fminf(x2, sm.sx2[j]) - fmaxf(x1, sm.sx1[j]) + 1.0f;
                float ih = fminf(y2, sm.sy2[j]) - fmaxf(y1, sm.sy1[j]) + 1.0f;
                iw = fmaxf(iw, 0.0f);
                ih = fmaxf(ih, 0.0f);
                float inter = iw * ih;
                float iou = inter / (ai + sm.sar[j] - inter);
                if (iou > NMS_THRESH) sup[j] = 1;
            }
            __syncthreads();
            ++i;
            while (i < nv && sup[i]) ++i;
        }
    }

    // ---- append kept entries (warp-aggregated global atomic, dense list) ----
    const int AIT = (nv + TMAIN - 1) / TMAIN;
    for (int it = 0; it < AIT; ++it) {
        int j = tid + it*TMAIN;
        bool kp = (j < nv) && ((sm.skeep[j >> 6] >> (j & 63)) & 1ull);
        unsigned m = __ballot_sync(FULL, kp);
        int base = 0;
        if (lane == 0 && m) base = atomicAdd(&g_kcount, __popc(m));
        base = __shfl_sync(FULL, base, 0);
        if (kp) {
            int p = base + __popc(m & ((1u << lane) - 1u));
            float4* L = reinterpret_cast<float4*>(g_list + (size_t)p*8);
            L[0] = make_float4(sm.ssc[j], (float)c, (float)j, sm.sx1[j]);
            L[1] = make_float4(sm.sy1[j], sm.sx2[j], sm.sy2[j], 0.f);
        }
    }
}

// ---------------- kernel 2: smem radix-select kth + scatter + reset ----------------
__global__ __launch_bounds__(TFIN) void k_final(float* __restrict__ out) {
    const int tid = threadIdx.x;
    const int lane = tid & 31, w = tid >> 5;
    const unsigned FULL = 0xFFFFFFFFu;

    __shared__ float ssc[SMEM_SC_CAP];
    __shared__ unsigned int cand[CAND_CAP];
    __shared__ int hist[256];
    __shared__ int wtot[8];
    __shared__ unsigned int s_prefix;
    __shared__ int s_need;
    __shared__ int s_ncand;
    __shared__ int s_cc;

    // PDL: launched before k_main finished; wait before consuming its output.
    cudaGridDependencySynchronize();

    const int count = g_kcount;

    int   filt = 0;
    float kth  = -CUDART_INF_F;

    if (count > MAX_DET) {
        const bool smem_path = (count <= SMEM_SC_CAP);
        if (tid == 0) { s_prefix = 0u; s_need = MAX_DET; s_cc = 0; s_ncand = 0; }
        if (tid < 256) hist[tid] = 0;
        __syncthreads();

        // fused pass: copy scores to smem AND build the level-0 histogram
        for (int j = tid; j < count; j += TFIN) {
            float v = g_list[(size_t)j*8];         // L0.x = score
            if (smem_path) ssc[j] = v;
            atomicAdd(&hist[mono_key(v) >> 24], 1);
        }
        __syncthreads();

        // ---- level 0 select (records the chosen bin's population) ----
        {
            const int need = s_need;
            int h = (tid < 256) ? hist[tid] : 0;
            int v = h;
            #pragma unroll
            for (int off = 1; off < 32; off <<= 1) {
                int u2 = __shfl_down_sync(FULL, v, off);
                if (lane + off < 32) v += u2;
            }
            if (lane == 0 && w < 8) wtot[w] = v;
            __syncthreads();
            if (tid < 256) {
                int add = 0;
                #pragma unroll
                for (int k = 0; k < 8; k++) if (k > w) add += wtot[k];
                int sfx = v + add;
                int hi  = sfx - h;
                if (sfx >= need && hi < need) {
                    s_prefix = (unsigned int)tid << 24;
                    s_need   = need - hi;
                    s_ncand  = h;                 // elements sharing the chosen top-8 prefix
                }
            }
            __syncthreads();
        }

        const int ncand = s_ncand;
        if (ncand <= CAND_CAP) {
            // ---- compact the candidates (ballot-aggregated) ----
            const unsigned int topbin = s_prefix >> 24;
            for (int j0 = 0; j0 < count; j0 += TFIN) {
                int j = j0 + tid;
                unsigned int u = 0;
                bool hit = false;
                if (j < count) {
                    u = mono_key(smem_path ? ssc[j] : g_list[(size_t)j*8]);
                    hit = (u >> 24) == topbin;
                }
                unsigned m = __ballot_sync(FULL, hit);
                int base = 0;
                if (lane == 0 && m) base = atomicAdd(&s_cc, __popc(m));
                base = __shfl_sync(FULL, base, 0);
                if (hit) cand[base + __popc(m & ((1u << lane) - 1u))] = u;
            }
            __syncthreads();

            // ---- levels 1..3 over the small candidate set ----
            #pragma unroll
            for (int level = 1; level < 4; ++level) {
                const int shift = 24 - 8*level;
                const unsigned int dmask = 0xFFFFFFFFu << (shift + 8);
                if (tid < 256) hist[tid] = 0;
                __syncthreads();
                const unsigned int pfx = s_prefix;
                for (int j = tid; j < ncand; j += TFIN) {
                    unsigned int u = cand[j];
                    if ((u & dmask) == pfx)
                        atomicAdd(&hist[(u >> shift) & 0xFFu], 1);
                }
                __syncthreads();
                const int need = s_need;
                int h = (tid < 256) ? hist[tid] : 0;
                int v = h;
                #pragma unroll
                for (int off = 1; off < 32; off <<= 1) {
                    int u2 = __shfl_down_sync(FULL, v, off);
                    if (lane + off < 32) v += u2;
                }
                if (lane == 0 && w < 8) wtot[w] = v;
                __syncthreads();
                if (tid < 256) {
                    int add = 0;
                    #pragma unroll
                    for (int k = 0; k < 8; k++) if (k > w) add += wtot[k];
                    int sfx = v + add;
                    int hi  = sfx - h;
                    if (sfx >= need && hi < need) {
                        s_prefix = pfx | ((unsigned int)tid << shift);
                        s_need   = need - hi;
                    }
                }
                __syncthreads();
            }
        } else {
            // fallback: full scans (pathological tie mass in one bin)
            #pragma unroll
            for (int level = 1; level < 4; ++level) {
                const int shift = 24 - 8*level;
                const unsigned int dmask = 0xFFFFFFFFu << (shift + 8);
                if (tid < 256) hist[tid] = 0;
                __syncthreads();
                const unsigned int pfx = s_prefix;
                for (int j = tid; j < count; j += TFIN) {
                    unsigned int u = mono_key(smem_path ? ssc[j] : g_list[(size_t)j*8]);
                    if ((u & dmask) == pfx)
                        atomicAdd(&hist[(u >> shift) & 0xFFu], 1);
                }
                __syncthreads();
                const int need = s_need;
                int h = (tid < 256) ? hist[tid] : 0;
                int v = h;
                #pragma unroll
                for (int off = 1; off < 32; off <<= 1) {
                    int u2 = __shfl_down_sync(FULL, v, off);
                    if (lane + off < 32) v += u2;
                }
                if (lane == 0 && w < 8) wtot[w] = v;
                __syncthreads();
                if (tid < 256) {
                    int add = 0;
                    #pragma unroll
                    for (int k = 0; k < 8; k++) if (k > w) add += wtot[k];
                    int sfx = v + add;
                    int hi  = sfx - h;
                    if (sfx >= need && hi < need) {
                        s_prefix = pfx | ((unsigned int)tid << shift);
                        s_need   = need - hi;
                    }
                }
                __syncthreads();
            }
        }
        filt = 1;
        kth  = inv_mono(s_prefix);        // exact value of the MAX_DET-th largest
    }

    // ---- scatter kept rows into the output ----
    for (int e = tid; e < count; e += TFIN) {
        const float4 L0 = reinterpret_cast<const float4*>(g_list + (size_t)e*8)[0];
        float s = L0.x;
        if (filt && !(s >= kth)) continue;
        const float4 L1 = reinterpret_cast<const float4*>(g_list + (size_t)e*8)[1];
        int c = (int)L0.y;
        int j = (int)L0.z;
        int r = c*NROI + j;
        float* d = out + (size_t)r*6;
        d[0] = 0.0f;
        d[1] = L0.w;  // x1
        d[2] = L1.x;  // y1
        d[3] = L1.y;  // x2
        d[4] = L1.z;  // y2
        d[5] = s;
        out[NTOT*7 + r] = 1.0f;   // keep flag
    }

    // ---- restore invariant for the next invocation ----
    __syncthreads();
    if (tid == 0) g_kcount = 0;
}

extern "C" void kernel_launch(void* const* d_in, const int* in_sizes, int n_in,
                              void* d_out, int out_size) {
    const float* rois   = (const float*)d_in[0];
    const float* delta  = (const float*)d_in[1];
    const float* prob   = (const float*)d_in[2];
    const float* iminfo = (const float*)d_in[3];
    float* out = (float*)d_out;

    static_assert(sizeof(SMem) < 100*1024, "smem budget");
    cudaFuncSetAttribute(k_main, cudaFuncAttributeMaxDynamicSharedMemorySize,
                         (int)sizeof(SMem));

    k_main<<<NCLS, TMAIN, sizeof(SMem)>>>(rois, delta, prob, iminfo, out);

    // k_final with programmatic dependent launch: its launch/prologue overlaps
    // k_main's tail; device-side cudaGridDependencySynchronize() provides the
    // ordering before it reads k_main's results.
    cudaLaunchConfig_t cfg = {};
    cfg.gridDim  = dim3(1, 1, 1);
    cfg.blockDim = dim3(TFIN, 1, 1);
    cfg.dynamicSmemBytes = 0;
    cfg.stream = 0;
    cudaLaunchAttribute attrs[1];
    attrs[0].id = cudaLaunchAttributeProgrammaticStreamSerialization;
    attrs[0].val.programmaticStreamSerializationAllowed = 1;
    cfg.attrs = attrs;
    cfg.numAttrs = 1;
    cudaLaunchKernelEx(&cfg, k_final, out);
}

// round 16
// speedup vs baseline: 1.1964x; 1.0286x over previous
#include <cuda_runtime.h>
#include <math_constants.h>

#define NROI   1500
#define NCLS   80          // foreground classes 1..80
#define NTOT   (NROI*NCLS) // 120000
#define SCORE_THRESH 0.05f
#define NMS_THRESH   0.5f
#define MAX_DET 100
#define CAP    1504        // max valid per class (<= NROI), padded
#define MASK_CAP 512       // bitmask NMS path supported up to this nv
#define RANK_CAP 512       // rank-sort path supported up to this nv
#define SMEM_SC_CAP 4096   // kept-score smem buffer in k_final
#define CAND_CAP 2048      // level-0 candidate buffer in k_final
#define TMAIN  1024
#define TFIN   1024
#define NWARP  (TMAIN/32)
#define REG_ENT 4          // register-prefetched entries per k_final thread

// Output float4 quads split across the NCLS blocks of k_main
#define QTOT   ((NTOT*8)/4)        // 240000
#define QPB    (QTOT/NCLS)         // 3000 per block

// ---------------- scratch (device globals; no allocation) ----------------
// g_kcount is zero-initialized at load and restored to 0 at the end of every
// k_final run -> every invocation (correctness, capture, replays) sees 0.
__device__ float g_list[NTOT*8];   // kept entries: {s, c, j, x1}{y1, x2, y2, 0}
__device__ int   g_kcount;

__device__ __forceinline__ unsigned int mono_key(float s) {
    unsigned int b = __float_as_uint(s);
    return (b & 0x80000000u) ? ~b : (b | 0x80000000u);
}
__device__ __forceinline__ float inv_mono(unsigned int u) {
    unsigned int b = (u & 0x80000000u) ? (u & 0x7FFFFFFFu) : ~u;
    return __uint_as_float(b);
}

// ---------------- kernel 1: fill + per-class compact+sort+decode+NMS ----------------
struct SMem {
    unsigned long long skey[2048];
    float sx1[CAP], sy1[CAP], sx2[CAP], sy2[CAP], sar[CAP], ssc[CAP];
    unsigned long long smask[MASK_CAP*8];  // reused as sup[] bytes in fallback
    unsigned long long skeep[24];
    int   cnt;
};

__global__ __launch_bounds__(TMAIN) void k_main(const float* __restrict__ rois,
                                                const float* __restrict__ delta,
                                                const float* __restrict__ prob,
                                                const float* __restrict__ iminfo,
                                                float* __restrict__ out) {
    extern __shared__ char smem_raw[];
    SMem& sm = *reinterpret_cast<SMem*>(smem_raw);
    const int c    = blockIdx.x;
    const int cls  = c + 1;
    const int tid  = threadIdx.x;
    const int lane = tid & 31;
    const int wid  = tid >> 5;
    const unsigned FULL = 0xFFFFFFFFu;

    if (tid == 0) sm.cnt = 0;
    // init visibility enforced by the barrier below (after prefetch/fill)

    // ---- prefetch this thread's prob entries + iminfo (latency hides behind fill) ----
    const int NIT = (NROI + TMAIN - 1) / TMAIN;   // 2
    float sv[NIT];
    #pragma unroll
    for (int it = 0; it < NIT; ++it) {
        int j = tid + it*TMAIN;
        sv[it] = (j < NROI) ? prob[(size_t)j*81 + cls] : 0.0f;
    }
    const float H = iminfo[0], W = iminfo[1];

    // ---- fill this block's 1/NCLS slice of the output ----
    // layout (float32): dets[NTOT*6]=0 | cls_idx[NTOT]=class | keep[NTOT]=0
    {
        float4* o4 = reinterpret_cast<float4*>(out);
        const int q0 = c*QPB, q1 = q0 + QPB;
        for (int q = q0 + tid; q < q1; q += TMAIN) {
            float4 v = make_float4(0.f,0.f,0.f,0.f);
            if (q >= (NTOT*6)/4 && q < (NTOT*7)/4) {
                int r0 = q*4 - NTOT*6;
                v.x = (float)((r0+0)/NROI + 1);
                v.y = (float)((r0+1)/NROI + 1);
                v.z = (float)((r0+2)/NROI + 1);
                v.w = (float)((r0+3)/NROI + 1);
            }
            o4[q] = v;
        }
    }
    __syncthreads();   // orders sm.cnt=0 before the atomics below

    // ---- compact valid entries (warp-aggregated shared atomic) ----
    #pragma unroll
    for (int it = 0; it < NIT; ++it) {
        int j = tid + it*TMAIN;
        bool valid = (j < NROI) && (sv[it] > SCORE_THRESH);
        unsigned m = __ballot_sync(FULL, valid);
        int base = 0;
        if (lane == 0 && m) base = atomicAdd(&sm.cnt, __popc(m));
        base = __shfl_sync(FULL, base, 0);
        if (valid) {
            int p = base + __popc(m & ((1u << lane) - 1u));
            sm.skey[p] = ((unsigned long long)mono_key(sv[it]) << 32)
                       | (unsigned long long)(0xFFFFFFFFu - (unsigned)j);
        }
    }
    __syncthreads();
    const int nv = sm.cnt;
    if (nv == 0) return;

    const float lx = W - 1.0f, ly = H - 1.0f;

    if (nv <= RANK_CAP) {
        // ---- rank sort + decode fused; global loads hoisted above rank loop ----
        for (int j = tid; j < nv; j += TMAIN) {
            unsigned long long k = sm.skey[j];
            int idx = (int)(0xFFFFFFFFu - (unsigned int)(k & 0xFFFFFFFFull));
            float s = inv_mono((unsigned int)(k >> 32));

            // issue global loads now; latency hides behind the rank loop below
            float rx1 = rois[idx*5+1], ry1 = rois[idx*5+2];
            float rx2 = rois[idx*5+3], ry2 = rois[idx*5+4];
            const float4 d4 = *reinterpret_cast<const float4*>(delta + (size_t)idx*(4*81) + 4*cls);

            int r = 0;
            int i = 0;
            for (; i + 4 <= nv; i += 4) {               // unrolled rank count
                r += (sm.skey[i]   > k);
                r += (sm.skey[i+1] > k);
                r += (sm.skey[i+2] > k);
                r += (sm.skey[i+3] > k);
            }
            for (; i < nv; i++) r += (sm.skey[i] > k);  // keys unique

            float w  = rx2 - rx1 + 1.0f;
            float h  = ry2 - ry1 + 1.0f;
            float cx = rx1 + 0.5f*w;
            float cy = ry1 + 0.5f*h;
            float dx = d4.x / 10.0f, dy = d4.y / 10.0f;
            float dw = d4.z / 5.0f,  dh = d4.w / 5.0f;
            float pcx = cx + w*dx;
            float pcy = cy + h*dy;
            float pw  = w * expf(dw);
            float ph  = h * expf(dh);
            float bx1 = fminf(fmaxf(pcx - 0.5f*pw,        0.0f), lx);
            float by1 = fminf(fmaxf(pcy - 0.5f*ph,        0.0f), ly);
            float bx2 = fminf(fmaxf(pcx + 0.5f*pw - 1.0f, 0.0f), lx);
            float by2 = fminf(fmaxf(pcy + 0.5f*ph - 1.0f, 0.0f), ly);

            sm.sx1[r] = bx1; sm.sy1[r] = by1; sm.sx2[r] = bx2; sm.sy2[r] = by2;
            sm.sar[r] = (bx2 - bx1 + 1.0f) * (by2 - by1 + 1.0f);
            sm.ssc[r] = s;
        }
        __syncthreads();
    } else {
        // ---- fallback: bitonic sort over m = next pow2 >= nv ----
        int m = 1; while (m < nv) m <<= 1;
        for (int j = nv + tid; j < m; j += TMAIN) sm.skey[j] = 0ull; // pads last
        __syncthreads();
        for (int size = 2; size <= m; size <<= 1) {
            for (int stride = size >> 1; stride > 0; stride >>= 1) {
                for (int t = tid; t < (m >> 1); t += TMAIN) {
                    int pos = 2*t - (t & (stride - 1));
                    bool desc = (pos & size) == 0;
                    unsigned long long a = sm.skey[pos], b = sm.skey[pos + stride];
                    if ((a < b) == desc) { sm.skey[pos] = b; sm.skey[pos + stride] = a; }
                }
                __syncthreads();
            }
        }
        for (int j = tid; j < nv; j += TMAIN) {
            unsigned long long k = sm.skey[j];
            int idx = (int)(0xFFFFFFFFu - (unsigned int)(k & 0xFFFFFFFFull));
            float s = inv_mono((unsigned int)(k >> 32));
            float rx1 = rois[idx*5+1], ry1 = rois[idx*5+2];
            float rx2 = rois[idx*5+3], ry2 = rois[idx*5+4];
            const float4 d4 = *reinterpret_cast<const float4*>(delta + (size_t)idx*(4*81) + 4*cls);
            float w  = rx2 - rx1 + 1.0f;
            float h  = ry2 - ry1 + 1.0f;
            float cx = rx1 + 0.5f*w;
            float cy = ry1 + 0.5f*h;
            float dx = d4.x / 10.0f, dy = d4.y / 10.0f;
            float dw = d4.z / 5.0f,  dh = d4.w / 5.0f;
            float pcx = cx + w*dx;
            float pcy = cy + h*dy;
            float pw  = w * expf(dw);
            float ph  = h * expf(dh);
            float bx1 = fminf(fmaxf(pcx - 0.5f*pw,        0.0f), lx);
            float by1 = fminf(fmaxf(pcy - 0.5f*ph,        0.0f), ly);
            float bx2 = fminf(fmaxf(pcx + 0.5f*pw - 1.0f, 0.0f), lx);
            float by2 = fminf(fmaxf(pcy + 0.5f*ph - 1.0f, 0.0f), ly);
            sm.sx1[j] = bx1; sm.sy1[j] = by1; sm.sx2[j] = bx2; sm.sy2[j] = by2;
            sm.sar[j] = (bx2 - bx1 + 1.0f) * (by2 - by1 + 1.0f);
            sm.ssc[j] = s;
        }
        __syncthreads();
    }

    // ---- NMS ----
    if (nv <= MASK_CAP) {
        // warp-per-row ballot mask build: lanes cover 64-bit word chunks
        const int MW = (nv + 63) >> 6;
        for (int i = wid; i < nv; i += NWARP) {
            float x1 = sm.sx1[i], y1 = sm.sy1[i], x2 = sm.sx2[i], y2 = sm.sy2[i];
            float ai = sm.sar[i];
            for (int ww = (i >> 6); ww < MW; ww++) {
                int j1 = ww*64 + lane;
                int j2 = j1 + 32;
                bool p1 = false, p2 = false;
                if (j1 > i && j1 < nv) {
                    float iw = fminf(x2, sm.sx2[j1]) - fmaxf(x1, sm.sx1[j1]) + 1.0f;
                    float ih = fminf(y2, sm.sy2[j1]) - fmaxf(y1, sm.sy1[j1]) + 1.0f;
                    iw = fmaxf(iw, 0.0f); ih = fmaxf(ih, 0.0f);
                    float inter = iw * ih;
                    p1 = (inter / (ai + sm.sar[j1] - inter)) > NMS_THRESH;
                }
                if (j2 > i && j2 < nv) {
                    float iw = fminf(x2, sm.sx2[j2]) - fmaxf(x1, sm.sx1[j2]) + 1.0f;
                    float ih = fminf(y2, sm.sy2[j2]) - fmaxf(y1, sm.sy1[j2]) + 1.0f;
                    iw = fmaxf(iw, 0.0f); ih = fmaxf(ih, 0.0f);
                    float inter = iw * ih;
                    p2 = (inter / (ai + sm.sar[j2] - inter)) > NMS_THRESH;
                }
                unsigned lo = __ballot_sync(FULL, p1);
                unsigned hi = __ballot_sync(FULL, p2);
                if (lane == 0)
                    sm.smask[i*8 + ww] = (unsigned long long)lo
                                       | ((unsigned long long)hi << 32);
            }
        }
        __syncthreads();
        if (tid == 0) {
            if (MW <= 2) {
                // scalar-register scan with depth-2 LDS prefetch: no local memory,
                // per-iteration chain is pure ALU.
                unsigned long long sup0 = 0ull, sup1 = 0ull;
                unsigned long long keep0 = 0ull, keep1 = 0ull;
                const int lim0 = (nv < 64) ? nv : 64;
                unsigned long long a0 = sm.smask[0], a1 = (MW > 1) ? sm.smask[1] : 0ull;
                unsigned long long b0 = 0ull, b1 = 0ull;
                if (nv > 1) { b0 = sm.smask[8]; b1 = (MW > 1) ? sm.smask[9] : 0ull; }
                for (int i = 0; i < lim0; i++) {
                    unsigned long long c0 = a0, c1 = a1;
                    a0 = b0; a1 = b1;
                    if (i + 2 < nv) {
                        int base = (i + 2)*8;
                        b0 = sm.smask[base];
                        b1 = (MW > 1) ? sm.smask[base + 1] : 0ull;
                    }
                    if (!((sup0 >> i) & 1ull)) {
                        keep0 |= 1ull << i;
                        sup0 |= c0;
                        sup1 |= c1;
                    }
                }
                if (nv > 64) {
                    unsigned long long a = sm.smask[64*8 + 1];
                    unsigned long long b = (nv > 65) ? sm.smask[65*8 + 1] : 0ull;
                    for (int i = 64; i < nv; i++) {
                        unsigned long long cc = a;
                        a = b;
                        if (i + 2 < nv) b = sm.smask[(i + 2)*8 + 1];
                        int bpos = i - 64;
                        if (!((sup1 >> bpos) & 1ull)) {
                            keep1 |= 1ull << bpos;
                            sup1 |= cc;
                        }
                    }
                }
                sm.skeep[0] = keep0;
                if (MW > 1) sm.skeep[1] = keep1;
            } else {
                unsigned long long keepw[8], supw[8];
                #pragma unroll
                for (int w = 0; w < 8; w++) { keepw[w] = 0ull; supw[w] = 0ull; }
                for (int i = 0; i < nv; i++) {
                    if (!((supw[i >> 6] >> (i & 63)) & 1ull)) {
                        keepw[i >> 6] |= (1ull << (i & 63));
                        for (int w = (i >> 6); w < MW; w++) supw[w] |= sm.smask[i*8 + w];
                    }
                }
                for (int w = 0; w < MW; w++) sm.skeep[w] = keepw[w];
            }
        }
        __syncthreads();
    } else {
        unsigned char* sup = reinterpret_cast<unsigned char*>(sm.smask);
        for (int j = tid; j < nv; j += TMAIN) sup[j] = 0;
        if (tid < 24) sm.skeep[tid] = 0ull;
        __syncthreads();
        int i = 0;
        while (i < nv) {
            if (tid == 0) sm.skeep[i >> 6] |= (1ull << (i & 63));
            float x1 = sm.sx1[i], y1 = sm.sy1[i], x2 = sm.sx2[i], y2 = sm.sy2[i];
            float ai = sm.sar[i];
            for (int j = i + 1 + tid; j < nv; j += TMAIN) {
                if (sup[j]) continue;
                float iw = fminf(x2, sm.sx2[j]) - fmaxf(x1, sm.sx1[j]) + 1.0f;
                float ih = fminf(y2, sm.sy2[j]) - fmaxf(y1, sm.sy1[j]) + 1.0f;
                iw = fmaxf(iw, 0.0f);
                ih = fmaxf(ih, 0.0f);
                float inter = iw * ih;
                float iou = inter / (ai + sm.sar[j] - inter);
                if (iou > NMS_THRESH) sup[j] = 1;
            }
            __syncthreads();
            ++i;
            while (i < nv && sup[i]) ++i;
        }
    }

    // ---- append kept entries (warp-aggregated global atomic, dense list) ----
    const int AIT = (nv + TMAIN - 1) / TMAIN;
    for (int it = 0; it < AIT; ++it) {
        int j = tid + it*TMAIN;
        bool kp = (j < nv) && ((sm.skeep[j >> 6] >> (j & 63)) & 1ull);
        unsigned m = __ballot_sync(FULL, kp);
        int base = 0;
        if (lane == 0 && m) base = atomicAdd(&g_kcount, __popc(m));
        base = __shfl_sync(FULL, base, 0);
        if (kp) {
            int p = base + __popc(m & ((1u << lane) - 1u));
            float4* L = reinterpret_cast<float4*>(g_list + (size_t)p*8);
            L[0] = make_float4(sm.ssc[j], (float)c, (float)j, sm.sx1[j]);
            L[1] = make_float4(sm.sy1[j], sm.sx2[j], sm.sy2[j], 0.f);
        }
    }
}

// ---------------- kernel 2: smem radix-select kth + scatter + reset ----------------
__global__ __launch_bounds__(TFIN) void k_final(float* __restrict__ out) {
    const int tid = threadIdx.x;
    const int lane = tid & 31, w = tid >> 5;
    const unsigned FULL = 0xFFFFFFFFu;

    __shared__ float ssc[SMEM_SC_CAP];
    __shared__ unsigned int cand[CAND_CAP];
    __shared__ int hist[256];
    __shared__ int wtot[8];
    __shared__ unsigned int s_prefix;
    __shared__ int s_need;
    __shared__ int s_ncand;
    __shared__ int s_cc;

    // PDL: launched before k_main finished; wait before consuming its output.
    cudaGridDependencySynchronize();

    const int count = g_kcount;   // dependent load; overlapped by inits below

    // shared inits hoisted before any count-dependent use (overlap LDG latency)
    if (tid == 0) { s_prefix = 0u; s_need = MAX_DET; s_cc = 0; s_ncand = 0; }
    if (tid < 256) hist[tid] = 0;

    // ---- unconditional register prefetch of scatter data ----
    // Covers count <= REG_ENT*TFIN = 4096 (same bound as smem_path).
    const bool reg_path = (count <= REG_ENT*TFIN);
    float4 rl0[REG_ENT], rl1[REG_ENT];
    if (reg_path) {
        #pragma unroll
        for (int it = 0; it < REG_ENT; ++it) {
            int j = tid + it*TFIN;
            if (j < count) {
                rl0[it] = reinterpret_cast<const float4*>(g_list + (size_t)j*8)[0];
                rl1[it] = reinterpret_cast<const float4*>(g_list + (size_t)j*8)[1];
            }
        }
    }

    int   filt = 0;
    float kth  = -CUDART_INF_F;

    if (count > MAX_DET) {
        const bool smem_path = (count <= SMEM_SC_CAP);
        __syncthreads();   // hist/s_* init visible

        // fused level-0 pass: scores from registers (reg_path) or global
        if (reg_path) {
            #pragma unroll
            for (int it = 0; it < REG_ENT; ++it) {
                int j = tid + it*TFIN;
                if (j < count) {
                    float v = rl0[it].x;
                    ssc[j] = v;                        // reg_path implies smem_path
                    atomicAdd(&hist[mono_key(v) >> 24], 1);
                }
            }
        } else {
            for (int j = tid; j < count; j += TFIN) {
                float v = g_list[(size_t)j*8];
                if (smem_path) ssc[j] = v;
                atomicAdd(&hist[mono_key(v) >> 24], 1);
            }
        }
        __syncthreads();

        // ---- level 0 select (records the chosen bin's population) ----
        {
            const int need = s_need;
            int h = (tid < 256) ? hist[tid] : 0;
            int v = h;
            #pragma unroll
            for (int off = 1; off < 32; off <<= 1) {
                int u2 = __shfl_down_sync(FULL, v, off);
                if (lane + off < 32) v += u2;
            }
            if (lane == 0 && w < 8) wtot[w] = v;
            __syncthreads();
            if (tid < 256) {
                int add = 0;
                #pragma unroll
                for (int k = 0; k < 8; k++) if (k > w) add += wtot[k];
                int sfx = v + add;
                int hi  = sfx - h;
                if (sfx >= need && hi < need) {
                    s_prefix = (unsigned int)tid << 24;
                    s_need   = need - hi;
                    s_ncand  = h;                 // elements sharing the chosen top-8 prefix
                }
            }
            __syncthreads();
        }

        const int ncand = s_ncand;
        if (ncand <= CAND_CAP) {
            // ---- compact the candidates (ballot-aggregated) ----
            const unsigned int topbin = s_prefix >> 24;
            for (int j0 = 0; j0 < count; j0 += TFIN) {
                int j = j0 + tid;
                unsigned int u = 0;
                bool hit = false;
                if (j < count) {
                    u = mono_key(smem_path ? ssc[j] : g_list[(size_t)j*8]);
                    hit = (u >> 24) == topbin;
                }
                unsigned m = __ballot_sync(FULL, hit);
                int base = 0;
                if (lane == 0 && m) base = atomicAdd(&s_cc, __popc(m));
                base = __shfl_sync(FULL, base, 0);
                if (hit) cand[base + __popc(m & ((1u << lane) - 1u))] = u;
            }
            __syncthreads();

            // ---- levels 1..3 over the small candidate set ----
            #pragma unroll
            for (int level = 1; level < 4; ++level) {
                const int shift = 24 - 8*level;
                const unsigned int dmask = 0xFFFFFFFFu << (shift + 8);
                if (tid < 256) hist[tid] = 0;
                __syncthreads();
                const unsigned int pfx = s_prefix;
                for (int j = tid; j < ncand; j += TFIN) {
                    unsigned int u = cand[j];
                    if ((u & dmask) == pfx)
                        atomicAdd(&hist[(u >> shift) & 0xFFu], 1);
                }
                __syncthreads();
                const int need = s_need;
                int h = (tid < 256) ? hist[tid] : 0;
                int v = h;
                #pragma unroll
                for (int off = 1; off < 32; off <<= 1) {
                    int u2 = __shfl_down_sync(FULL, v, off);
                    if (lane + off < 32) v += u2;
                }
                if (lane == 0 && w < 8) wtot[w] = v;
                __syncthreads();
                if (tid < 256) {
                    int add = 0;
                    #pragma unroll
                    for (int k = 0; k < 8; k++) if (k > w) add += wtot[k];
                    int sfx = v + add;
                    int hi  = sfx - h;
                    if (sfx >= need && hi < need) {
                        s_prefix = pfx | ((unsigned int)tid << shift);
                        s_need   = need - hi;
                    }
                }
                __syncthreads();
            }
        } else {
            // fallback: full scans (pathological tie mass in one bin)
            #pragma unroll
            for (int level = 1; level < 4; ++level) {
                const int shift = 24 - 8*level;
                const unsigned int dmask = 0xFFFFFFFFu << (shift + 8);
                if (tid < 256) hist[tid] = 0;
                __syncthreads();
                const unsigned int pfx = s_prefix;
                for (int j = tid; j < count; j += TFIN) {
                    unsigned int u = mono_key(smem_path ? ssc[j] : g_list[(size_t)j*8]);
                    if ((u & dmask) == pfx)
                        atomicAdd(&hist[(u >> shift) & 0xFFu], 1);
                }
                __syncthreads();
                const int need = s_need;
                int h = (tid < 256) ? hist[tid] : 0;
                int v = h;
                #pragma unroll
                for (int off = 1; off < 32; off <<= 1) {
                    int u2 = __shfl_down_sync(FULL, v, off);
                    if (lane + off < 32) v += u2;
                }
                if (lane == 0 && w < 8) wtot[w] = v;
                __syncthreads();
                if (tid < 256) {
                    int add = 0;
                    #pragma unroll
                    for (int k = 0; k < 8; k++) if (k > w) add += wtot[k];
                    int sfx = v + add;
                    int hi  = sfx - h;
                    if (sfx >= need && hi < need) {
                        s_prefix = pfx | ((unsigned int)tid << shift);
                        s_need   = need - hi;
                    }
                }
                __syncthreads();
            }
        }
        filt = 1;
        kth  = inv_mono(s_prefix);        // exact value of the MAX_DET-th largest
    }

    // ---- scatter kept rows into the output ----
    if (reg_path) {
        // pure register -> global stores; no dependent loads in the tail
        #pragma unroll
        for (int it = 0; it < REG_ENT; ++it) {
            int j = tid + it*TFIN;
            if (j < count) {
                float s = rl0[it].x;
                if (!filt || (s >= kth)) {
                    int cc = (int)rl0[it].y;
                    int jj = (int)rl0[it].z;
                    int r = cc*NROI + jj;
                    float* d = out + (size_t)r*6;
                    d[0] = 0.0f;
                    d[1] = rl0[it].w;  // x1
                    d[2] = rl1[it].x;  // y1
                    d[3] = rl1[it].y;  // x2
                    d[4] = rl1[it].z;  // y2
                    d[5] = s;
                    out[NTOT*7 + r] = 1.0f;   // keep flag
                }
            }
        }
    } else {
        for (int e = tid; e < count; e += TFIN) {
            const float4 L0 = reinterpret_cast<const float4*>(g_list + (size_t)e*8)[0];
            float s = L0.x;
            if (filt && !(s >= kth)) continue;
            const float4 L1 = reinterpret_cast<const float4*>(g_list + (size_t)e*8)[1];
            int cc = (int)L0.y;
            int jj = (int)L0.z;
            int r = cc*NROI + jj;
            float* d = out + (size_t)r*6;
            d[0] = 0.0f;
            d[1] = L0.w;  // x1
            d[2] = L1.x;  // y1
            d[3] = L1.y;  // x2
            d[4] = L1.z;  // y2
            d[5] = s;
            out[NTOT*7 + r] = 1.0f;   // keep flag
        }
    }

    // ---- restore invariant for the next invocation ----
    __syncthreads();
    if (tid == 0) g_kcount = 0;
}

extern "C" void kernel_launch(void* const* d_in, const int* in_sizes, int n_in,
                              void* d_out, int out_size) {
    const float* rois   = (const float*)d_in[0];
    const float* delta  = (const float*)d_in[1];
    const float* prob   = (const float*)d_in[2];
    const float* iminfo = (const float*)d_in[3];
    float* out = (float*)d_out;

    static_assert(sizeof(SMem) < 100*1024, "smem budget");
    cudaFuncSetAttribute(k_main, cudaFuncAttributeMaxDynamicSharedMemorySize,
                         (int)sizeof(SMem));

    k_main<<<NCLS, TMAIN, sizeof(SMem)>>>(rois, delta, prob, iminfo, out);

    // k_final with programmatic dependent launch: its launch/prologue overlaps
    // k_main's tail; device-side cudaGridDependencySynchronize() provides the
    // ordering before it reads k_main's results.
    cudaLaunchConfig_t cfg = {};
    cfg.gridDim  = dim3(1, 1, 1);
    cfg.blockDim = dim3(TFIN, 1, 1);
    cfg.dynamicSmemBytes = 0;
    cfg.stream = 0;
    cudaLaunchAttribute attrs[1];
    attrs[0].id = cudaLaunchAttributeProgrammaticStreamSerialization;
    attrs[0].val.programmaticStreamSerializationAllowed = 1;
    cfg.attrs = attrs;
    cfg.numAttrs = 1;
    cudaLaunchKernelEx(&cfg, k_final, out);
}

// round 17
// speedup vs baseline: 1.2742x; 1.0651x over previous
#include <cuda_runtime.h>
#include <math_constants.h>

#define NROI   1500
#define NCLS   80          // foreground classes 1..80
#define NTOT   (NROI*NCLS) // 120000
#define SCORE_THRESH 0.05f
#define NMS_THRESH   0.5f
#define MAX_DET 100
#define CAP    1504        // max valid per class (<= NROI), padded
#define MASK_CAP 512       // bitmask NMS path supported up to this nv
#define RANK_CAP 512       // rank-sort path supported up to this nv
#define SMEM_SC_CAP 4096   // kept-score smem buffer in k_final
#define CAND_CAP 2048      // level-0 candidate buffer in k_final
#define TMAIN  1024
#define TFIN   1024
#define NWARP  (TMAIN/32)
#define REG_ENT 4          // register-prefetched entries per k_final thread

// Output float4 quads split across the NCLS blocks of k_main
#define QTOT   ((NTOT*8)/4)        // 240000
#define QPB    (QTOT/NCLS)         // 3000 per block

// ---------------- scratch (device globals; no allocation) ----------------
// g_kcount is zero-initialized at load and restored to 0 at the end of every
// k_final run -> every invocation (correctness, capture, replays) sees 0.
__device__ float g_list[NTOT*8];   // kept entries: {s, c, j, x1}{y1, x2, y2, 0}
__device__ int   g_kcount;

__device__ __forceinline__ unsigned int mono_key(float s) {
    unsigned int b = __float_as_uint(s);
    return (b & 0x80000000u) ? ~b : (b | 0x80000000u);
}
__device__ __forceinline__ float inv_mono(unsigned int u) {
    unsigned int b = (u & 0x80000000u) ? (u & 0x7FFFFFFFu) : ~u;
    return __uint_as_float(b);
}
__device__ __forceinline__ void prefetch_l1(const void* p) {
    asm volatile("prefetch.global.L1 [%0];" :: "l"(p));
}

// ---------------- kernel 1: fill + per-class compact+sort+decode+NMS ----------------
struct SMem {
    unsigned long long skey[2048];
    float sx1[CAP], sy1[CAP], sx2[CAP], sy2[CAP], sar[CAP], ssc[CAP];
    unsigned long long smask[MASK_CAP*8];  // reused as sup[] bytes in fallback
    unsigned long long skeep[24];
    int   cnt;
};

__global__ __launch_bounds__(TMAIN) void k_main(const float* __restrict__ rois,
                                                const float* __restrict__ delta,
                                                const float* __restrict__ prob,
                                                const float* __restrict__ iminfo,
                                                float* __restrict__ out) {
    extern __shared__ char smem_raw[];
    SMem& sm = *reinterpret_cast<SMem*>(smem_raw);
    const int c    = blockIdx.x;
    const int cls  = c + 1;
    const int tid  = threadIdx.x;
    const int lane = tid & 31;
    const int wid  = tid >> 5;
    const unsigned FULL = 0xFFFFFFFFu;

    if (tid == 0) sm.cnt = 0;
    // init visibility enforced by the barrier below (after prefetch/fill)

    // ---- prefetch this thread's prob entries + iminfo (latency hides behind fill) ----
    const int NIT = (NROI + TMAIN - 1) / TMAIN;   // 2
    float sv[NIT];
    #pragma unroll
    for (int it = 0; it < NIT; ++it) {
        int j = tid + it*TMAIN;
        sv[it] = (j < NROI) ? prob[(size_t)j*81 + cls] : 0.0f;
    }
    const float H = iminfo[0], W = iminfo[1];

    // ---- fill this block's 1/NCLS slice of the output ----
    // layout (float32): dets[NTOT*6]=0 | cls_idx[NTOT]=class | keep[NTOT]=0
    {
        float4* o4 = reinterpret_cast<float4*>(out);
        const int q0 = c*QPB, q1 = q0 + QPB;
        for (int q = q0 + tid; q < q1; q += TMAIN) {
            float4 v = make_float4(0.f,0.f,0.f,0.f);
            if (q >= (NTOT*6)/4 && q < (NTOT*7)/4) {
                int r0 = q*4 - NTOT*6;
                v.x = (float)((r0+0)/NROI + 1);
                v.y = (float)((r0+1)/NROI + 1);
                v.z = (float)((r0+2)/NROI + 1);
                v.w = (float)((r0+3)/NROI + 1);
            }
            o4[q] = v;
        }
    }
    __syncthreads();   // orders sm.cnt=0 before the atomics below

    // ---- compact valid entries (warp-aggregated shared atomic) ----
    // Also warm L1 with the exact rois/delta lines the decode phase will gather:
    // fire-and-forget prefetches, consumed ~1 barrier + rank loop later.
    #pragma unroll
    for (int it = 0; it < NIT; ++it) {
        int j = tid + it*TMAIN;
        bool valid = (j < NROI) && (sv[it] > SCORE_THRESH);
        unsigned m = __ballot_sync(FULL, valid);
        int base = 0;
        if (lane == 0 && m) base = atomicAdd(&sm.cnt, __popc(m));
        base = __shfl_sync(FULL, base, 0);
        if (valid) {
            int p = base + __popc(m & ((1u << lane) - 1u));
            sm.skey[p] = ((unsigned long long)mono_key(sv[it]) << 32)
                       | (unsigned long long)(0xFFFFFFFFu - (unsigned)j);
            prefetch_l1(rois + j*5 + 1);
            prefetch_l1(rois + j*5 + 4);
            prefetch_l1(delta + (size_t)j*(4*81) + 4*cls);
        }
    }
    __syncthreads();
    const int nv = sm.cnt;
    if (nv == 0) return;

    const float lx = W - 1.0f, ly = H - 1.0f;

    if (nv <= RANK_CAP) {
        // ---- rank sort + decode fused; gathers hit prefetched L1 lines ----
        for (int j = tid; j < nv; j += TMAIN) {
            unsigned long long k = sm.skey[j];
            int idx = (int)(0xFFFFFFFFu - (unsigned int)(k & 0xFFFFFFFFull));
            float s = inv_mono((unsigned int)(k >> 32));

            // issue loads now; latency (L1-warm) hides behind the rank loop below
            float rx1 = rois[idx*5+1], ry1 = rois[idx*5+2];
            float rx2 = rois[idx*5+3], ry2 = rois[idx*5+4];
            const float4 d4 = *reinterpret_cast<const float4*>(delta + (size_t)idx*(4*81) + 4*cls);

            int r = 0;
            int i = 0;
            for (; i + 4 <= nv; i += 4) {               // unrolled rank count
                r += (sm.skey[i]   > k);
                r += (sm.skey[i+1] > k);
                r += (sm.skey[i+2] > k);
                r += (sm.skey[i+3] > k);
            }
            for (; i < nv; i++) r += (sm.skey[i] > k);  // keys unique

            float w  = rx2 - rx1 + 1.0f;
            float h  = ry2 - ry1 + 1.0f;
            float cx = rx1 + 0.5f*w;
            float cy = ry1 + 0.5f*h;
            float dx = d4.x / 10.0f, dy = d4.y / 10.0f;
            float dw = d4.z / 5.0f,  dh = d4.w / 5.0f;
            float pcx = cx + w*dx;
            float pcy = cy + h*dy;
            float pw  = w * expf(dw);
            float ph  = h * expf(dh);
            float bx1 = fminf(fmaxf(pcx - 0.5f*pw,        0.0f), lx);
            float by1 = fminf(fmaxf(pcy - 0.5f*ph,        0.0f), ly);
            float bx2 = fminf(fmaxf(pcx + 0.5f*pw - 1.0f, 0.0f), lx);
            float by2 = fminf(fmaxf(pcy + 0.5f*ph - 1.0f, 0.0f), ly);

            sm.sx1[r] = bx1; sm.sy1[r] = by1; sm.sx2[r] = bx2; sm.sy2[r] = by2;
            sm.sar[r] = (bx2 - bx1 + 1.0f) * (by2 - by1 + 1.0f);
            sm.ssc[r] = s;
        }
        __syncthreads();
    } else {
        // ---- fallback: bitonic sort over m = next pow2 >= nv ----
        int m = 1; while (m < nv) m <<= 1;
        for (int j = nv + tid; j < m; j += TMAIN) sm.skey[j] = 0ull; // pads last
        __syncthreads();
        for (int size = 2; size <= m; size <<= 1) {
            for (int stride = size >> 1; stride > 0; stride >>= 1) {
                for (int t = tid; t < (m >> 1); t += TMAIN) {
                    int pos = 2*t - (t & (stride - 1));
                    bool desc = (pos & size) == 0;
                    unsigned long long a = sm.skey[pos], b = sm.skey[pos + stride];
                    if ((a < b) == desc) { sm.skey[pos] = b; sm.skey[pos + stride] = a; }
                }
                __syncthreads();
            }
        }
        for (int j = tid; j < nv; j += TMAIN) {
            unsigned long long k = sm.skey[j];
            int idx = (int)(0xFFFFFFFFu - (unsigned int)(k & 0xFFFFFFFFull));
            float s = inv_mono((unsigned int)(k >> 32));
            float rx1 = rois[idx*5+1], ry1 = rois[idx*5+2];
            float rx2 = rois[idx*5+3], ry2 = rois[idx*5+4];
            const float4 d4 = *reinterpret_cast<const float4*>(delta + (size_t)idx*(4*81) + 4*cls);
            float w  = rx2 - rx1 + 1.0f;
            float h  = ry2 - ry1 + 1.0f;
            float cx = rx1 + 0.5f*w;
            float cy = ry1 + 0.5f*h;
            float dx = d4.x / 10.0f, dy = d4.y / 10.0f;
            float dw = d4.z / 5.0f,  dh = d4.w / 5.0f;
            float pcx = cx + w*dx;
            float pcy = cy + h*dy;
            float pw  = w * expf(dw);
            float ph  = h * expf(dh);
            float bx1 = fminf(fmaxf(pcx - 0.5f*pw,        0.0f), lx);
            float by1 = fminf(fmaxf(pcy - 0.5f*ph,        0.0f), ly);
            float bx2 = fminf(fmaxf(pcx + 0.5f*pw - 1.0f, 0.0f), lx);
            float by2 = fminf(fmaxf(pcy + 0.5f*ph - 1.0f, 0.0f), ly);
            sm.sx1[j] = bx1; sm.sy1[j] = by1; sm.sx2[j] = bx2; sm.sy2[j] = by2;
            sm.sar[j] = (bx2 - bx1 + 1.0f) * (by2 - by1 + 1.0f);
            sm.ssc[j] = s;
        }
        __syncthreads();
    }

    // ---- NMS ----
    if (nv <= MASK_CAP) {
        // warp-per-row ballot mask build: lanes cover 64-bit word chunks
        const int MW = (nv + 63) >> 6;
        for (int i = wid; i < nv; i += NWARP) {
            float x1 = sm.sx1[i], y1 = sm.sy1[i], x2 = sm.sx2[i], y2 = sm.sy2[i];
            float ai = sm.sar[i];
            for (int ww = (i >> 6); ww < MW; ww++) {
                int j1 = ww*64 + lane;
                int j2 = j1 + 32;
                bool p1 = false, p2 = false;
                if (j1 > i && j1 < nv) {
                    float iw = fminf(x2, sm.sx2[j1]) - fmaxf(x1, sm.sx1[j1]) + 1.0f;
                    float ih = fminf(y2, sm.sy2[j1]) - fmaxf(y1, sm.sy1[j1]) + 1.0f;
                    iw = fmaxf(iw, 0.0f); ih = fmaxf(ih, 0.0f);
                    float inter = iw * ih;
                    p1 = (inter / (ai + sm.sar[j1] - inter)) > NMS_THRESH;
                }
                if (j2 > i && j2 < nv) {
                    float iw = fminf(x2, sm.sx2[j2]) - fmaxf(x1, sm.sx1[j2]) + 1.0f;
                    float ih = fminf(y2, sm.sy2[j2]) - fmaxf(y1, sm.sy1[j2]) + 1.0f;
                    iw = fmaxf(iw, 0.0f); ih = fmaxf(ih, 0.0f);
                    float inter = iw * ih;
                    p2 = (inter / (ai + sm.sar[j2] - inter)) > NMS_THRESH;
                }
                unsigned lo = __ballot_sync(FULL, p1);
                unsigned hi = __ballot_sync(FULL, p2);
                if (lane == 0)
                    sm.smask[i*8 + ww] = (unsigned long long)lo
                                       | ((unsigned long long)hi << 32);
            }
        }
        __syncthreads();
        if (tid == 0) {
            if (MW <= 2) {
                // scalar-register scan with depth-2 LDS prefetch: no local memory,
                // per-iteration chain is pure ALU.
                unsigned long long sup0 = 0ull, sup1 = 0ull;
                unsigned long long keep0 = 0ull, keep1 = 0ull;
                const int lim0 = (nv < 64) ? nv : 64;
                unsigned long long a0 = sm.smask[0], a1 = (MW > 1) ? sm.smask[1] : 0ull;
                unsigned long long b0 = 0ull, b1 = 0ull;
                if (nv > 1) { b0 = sm.smask[8]; b1 = (MW > 1) ? sm.smask[9] : 0ull; }
                for (int i = 0; i < lim0; i++) {
                    unsigned long long c0 = a0, c1 = a1;
                    a0 = b0; a1 = b1;
                    if (i + 2 < nv) {
                        int base = (i + 2)*8;
                        b0 = sm.smask[base];
                        b1 = (MW > 1) ? sm.smask[base + 1] : 0ull;
                    }
                    if (!((sup0 >> i) & 1ull)) {
                        keep0 |= 1ull << i;
                        sup0 |= c0;
                        sup1 |= c1;
                    }
                }
                if (nv > 64) {
                    unsigned long long a = sm.smask[64*8 + 1];
                    unsigned long long b = (nv > 65) ? sm.smask[65*8 + 1] : 0ull;
                    for (int i = 64; i < nv; i++) {
                        unsigned long long cc = a;
                        a = b;
                        if (i + 2 < nv) b = sm.smask[(i + 2)*8 + 1];
                        int bpos = i - 64;
                        if (!((sup1 >> bpos) & 1ull)) {
                            keep1 |= 1ull << bpos;
                            sup1 |= cc;
                        }
                    }
                }
                sm.skeep[0] = keep0;
                if (MW > 1) sm.skeep[1] = keep1;
            } else {
                unsigned long long keepw[8], supw[8];
                #pragma unroll
                for (int w = 0; w < 8; w++) { keepw[w] = 0ull; supw[w] = 0ull; }
                for (int i = 0; i < nv; i++) {
                    if (!((supw[i >> 6] >> (i & 63)) & 1ull)) {
                        keepw[i >> 6] |= (1ull << (i & 63));
                        for (int w = (i >> 6); w < MW; w++) supw[w] |= sm.smask[i*8 + w];
                    }
                }
                for (int w = 0; w < MW; w++) sm.skeep[w] = keepw[w];
            }
        }
        __syncthreads();
    } else {
        unsigned char* sup = reinterpret_cast<unsigned char*>(sm.smask);
        for (int j = tid; j < nv; j += TMAIN) sup[j] = 0;
        if (tid < 24) sm.skeep[tid] = 0ull;
        __syncthreads();
        int i = 0;
        while (i < nv) {
            if (tid == 0) sm.skeep[i >> 6] |= (1ull << (i & 63));
            float x1 = sm.sx1[i], y1 = sm.sy1[i], x2 = sm.sx2[i], y2 = sm.sy2[i];
            float ai = sm.sar[i];
            for (int j = i + 1 + tid; j < nv; j += TMAIN) {
                if (sup[j]) continue;
                float iw = fminf(x2, sm.sx2[j]) - fmaxf(x1, sm.sx1[j]) + 1.0f;
                float ih = fminf(y2, sm.sy2[j]) - fmaxf(y1, sm.sy1[j]) + 1.0f;
                iw = fmaxf(iw, 0.0f);
                ih = fmaxf(ih, 0.0f);
                float inter = iw * ih;
                float iou = inter / (ai + sm.sar[j] - inter);
                if (iou > NMS_THRESH) sup[j] = 1;
            }
            __syncthreads();
            ++i;
            while (i < nv && sup[i]) ++i;
        }
    }

    // ---- append kept entries (warp-aggregated global atomic, dense list) ----
    const int AIT = (nv + TMAIN - 1) / TMAIN;
    for (int it = 0; it < AIT; ++it) {
        int j = tid + it*TMAIN;
        bool kp = (j < nv) && ((sm.skeep[j >> 6] >> (j & 63)) & 1ull);
        unsigned m = __ballot_sync(FULL, kp);
        int base = 0;
        if (lane == 0 && m) base = atomicAdd(&g_kcount, __popc(m));
        base = __shfl_sync(FULL, base, 0);
        if (kp) {
            int p = base + __popc(m & ((1u << lane) - 1u));
            float4* L = reinterpret_cast<float4*>(g_list + (size_t)p*8);
            L[0] = make_float4(sm.ssc[j], (float)c, (float)j, sm.sx1[j]);
            L[1] = make_float4(sm.sy1[j], sm.sx2[j], sm.sy2[j], 0.f);
        }
    }
}

// ---------------- kernel 2: smem radix-select kth + scatter + reset ----------------
__global__ __launch_bounds__(TFIN) void k_final(float* __restrict__ out) {
    const int tid = threadIdx.x;
    const int lane = tid & 31, w = tid >> 5;
    const unsigned FULL = 0xFFFFFFFFu;

    __shared__ float ssc[SMEM_SC_CAP];
    __shared__ unsigned int cand[CAND_CAP];
    __shared__ int hist[256];
    __shared__ int wtot[8];
    __shared__ unsigned int s_prefix;
    __shared__ int s_need;
    __shared__ int s_ncand;
    __shared__ int s_cc;

    // PDL: launched before k_main finished; wait before consuming its output.
    cudaGridDependencySynchronize();

    const int count = g_kcount;   // dependent load; overlapped by inits below

    // shared inits hoisted before any count-dependent use (overlap LDG latency)
    if (tid == 0) { s_prefix = 0u; s_need = MAX_DET; s_cc = 0; s_ncand = 0; }
    if (tid < 256) hist[tid] = 0;

    // ---- unconditional register prefetch of scatter data ----
    // Covers count <= REG_ENT*TFIN = 4096 (same bound as smem_path).
    const bool reg_path = (count <= REG_ENT*TFIN);
    float4 rl0[REG_ENT], rl1[REG_ENT];
    if (reg_path) {
        #pragma unroll
        for (int it = 0; it < REG_ENT; ++it) {
            int j = tid + it*TFIN;
            if (j < count) {
                rl0[it] = reinterpret_cast<const float4*>(g_list + (size_t)j*8)[0];
                rl1[it] = reinterpret_cast<const float4*>(g_list + (size_t)j*8)[1];
            }
        }
    }

    int   filt = 0;
    float kth  = -CUDART_INF_F;

    if (count > MAX_DET) {
        const bool smem_path = (count <= SMEM_SC_CAP);
        __syncthreads();   // hist/s_* init visible

        // fused level-0 pass: scores from registers (reg_path) or global
        if (reg_path) {
            #pragma unroll
            for (int it = 0; it < REG_ENT; ++it) {
                int j = tid + it*TFIN;
                if (j < count) {
                    float v = rl0[it].x;
                    ssc[j] = v;                        // reg_path implies smem_path
                    atomicAdd(&hist[mono_key(v) >> 24], 1);
                }
            }
        } else {
            for (int j = tid; j < count; j += TFIN) {
                float v = g_list[(size_t)j*8];
                if (smem_path) ssc[j] = v;
                atomicAdd(&hist[mono_key(v) >> 24], 1);
            }
        }
        __syncthreads();

        // ---- level 0 select (records the chosen bin's population) ----
        {
            const int need = s_need;
            int h = (tid < 256) ? hist[tid] : 0;
            int v = h;
            #pragma unroll
            for (int off = 1; off < 32; off <<= 1) {
                int u2 = __shfl_down_sync(FULL, v, off);
                if (lane + off < 32) v += u2;
            }
            if (lane == 0 && w < 8) wtot[w] = v;
            __syncthreads();
            if (tid < 256) {
                int add = 0;
                #pragma unroll
                for (int k = 0; k < 8; k++) if (k > w) add += wtot[k];
                int sfx = v + add;
                int hi  = sfx - h;
                if (sfx >= need && hi < need) {
                    s_prefix = (unsigned int)tid << 24;
                    s_need   = need - hi;
                    s_ncand  = h;                 // elements sharing the chosen top-8 prefix
                }
            }
            __syncthreads();
        }

        const int ncand = s_ncand;
        if (ncand <= CAND_CAP) {
            // ---- compact the candidates (ballot-aggregated) ----
            const unsigned int topbin = s_prefix >> 24;
            for (int j0 = 0; j0 < count; j0 += TFIN) {
                int j = j0 + tid;
                unsigned int u = 0;
                bool hit = false;
                if (j < count) {
                    u = mono_key(smem_path ? ssc[j] : g_list[(size_t)j*8]);
                    hit = (u >> 24) == topbin;
                }
                unsigned m = __ballot_sync(FULL, hit);
                int base = 0;
                if (lane == 0 && m) base = atomicAdd(&s_cc, __popc(m));
                base = __shfl_sync(FULL, base, 0);
                if (hit) cand[base + __popc(m & ((1u << lane) - 1u))] = u;
            }
            __syncthreads();

            // ---- levels 1..3 over the small candidate set ----
            #pragma unroll
            for (int level = 1; level < 4; ++level) {
                const int shift = 24 - 8*level;
                const unsigned int dmask = 0xFFFFFFFFu << (shift + 8);
                if (tid < 256) hist[tid] = 0;
                __syncthreads();
                const unsigned int pfx = s_prefix;
                for (int j = tid; j < ncand; j += TFIN) {
                    unsigned int u = cand[j];
                    if ((u & dmask) == pfx)
                        atomicAdd(&hist[(u >> shift) & 0xFFu], 1);
                }
                __syncthreads();
                const int need = s_need;
                int h = (tid < 256) ? hist[tid] : 0;
                int v = h;
                #pragma unroll
                for (int off = 1; off < 32; off <<= 1) {
                    int u2 = __shfl_down_sync(FULL, v, off);
                    if (lane + off < 32) v += u2;
                }
                if (lane == 0 && w < 8) wtot[w] = v;
                __syncthreads();
                if (tid < 256) {
                    int add = 0;
                    #pragma unroll
                    for (int k = 0; k < 8; k++) if (k > w) add += wtot[k];
                    int sfx = v + add;
                    int hi  = sfx - h;
                    if (sfx >= need && hi < need) {
                        s_prefix = pfx | ((unsigned int)tid << shift);
                        s_need   = need - hi;
                    }
                }
                __syncthreads();
            }
        } else {
            // fallback: full scans (pathological tie mass in one bin)
            #pragma unroll
            for (int level = 1; level < 4; ++level) {
                const int shift = 24 - 8*level;
                const unsigned int dmask = 0xFFFFFFFFu << (shift + 8);
                if (tid < 256) hist[tid] = 0;
                __syncthreads();
                const unsigned int pfx = s_prefix;
                for (int j = tid; j < count; j += TFIN) {
                    unsigned int u = mono_key(smem_path ? ssc[j] : g_list[(size_t)j*8]);
                    if ((u & dmask) == pfx)
                        atomicAdd(&hist[(u >> shift) & 0xFFu], 1);
                }
                __syncthreads();
                const int need = s_need;
                int h = (tid < 256) ? hist[tid] : 0;
                int v = h;
                #pragma unroll
                for (int off = 1; off < 32; off <<= 1) {
                    int u2 = __shfl_down_sync(FULL, v, off);
                    if (lane + off < 32) v += u2;
                }
                if (lane == 0 && w < 8) wtot[w] = v;
                __syncthreads();
                if (tid < 256) {
                    int add = 0;
                    #pragma unroll
                    for (int k = 0; k < 8; k++) if (k > w) add += wtot[k];
                    int sfx = v + add;
                    int hi  = sfx - h;
                    if (sfx >= need && hi < need) {
                        s_prefix = pfx | ((unsigned int)tid << shift);
                        s_need   = need - hi;
                    }
                }
                __syncthreads();
            }
        }
        filt = 1;
        kth  = inv_mono(s_prefix);        // exact value of the MAX_DET-th largest
    }

    // ---- scatter kept rows into the output ----
    if (reg_path) {
        // pure register -> global stores; no dependent loads in the tail
        #pragma unroll
        for (int it = 0; it < REG_ENT; ++it) {
            int j = tid + it*TFIN;
            if (j < count) {
                float s = rl0[it].x;
                if (!filt || (s >= kth)) {
                    int cc = (int)rl0[it].y;
                    int jj = (int)rl0[it].z;
                    int r = cc*NROI + jj;
                    float* d = out + (size_t)r*6;
                    d[0] = 0.0f;
                    d[1] = rl0[it].w;  // x1
                    d[2] = rl1[it].x;  // y1
                    d[3] = rl1[it].y;  // x2
                    d[4] = rl1[it].z;  // y2
                    d[5] = s;
                    out[NTOT*7 + r] = 1.0f;   // keep flag
                }
            }
        }
    } else {
        for (int e = tid; e < count; e += TFIN) {
            const float4 L0 = reinterpret_cast<const float4*>(g_list + (size_t)e*8)[0];
            float s = L0.x;
            if (filt && !(s >= kth)) continue;
            const float4 L1 = reinterpret_cast<const float4*>(g_list + (size_t)e*8)[1];
            int cc = (int)L0.y;
            int jj = (int)L0.z;
            int r = cc*NROI + jj;
            float* d = out + (size_t)r*6;
            d[0] = 0.0f;
            d[1] = L0.w;  // x1
            d[2] = L1.x;  // y1
            d[3] = L1.y;  // x2
            d[4] = L1.z;  // y2
            d[5] = s;
            out[NTOT*7 + r] = 1.0f;   // keep flag
        }
    }

    // ---- restore invariant for the next invocation ----
    __syncthreads();
    if (tid == 0) g_kcount = 0;
}

extern "C" void kernel_launch(void* const* d_in, const int* in_sizes, int n_in,
                              void* d_out, int out_size) {
    const float* rois   = (const float*)d_in[0];
    const float* delta  = (const float*)d_in[1];
    const float* prob   = (const float*)d_in[2];
    const float* iminfo = (const float*)d_in[3];
    float* out = (float*)d_out;

    static_assert(sizeof(SMem) < 100*1024, "smem budget");
    cudaFuncSetAttribute(k_main, cudaFuncAttributeMaxDynamicSharedMemorySize,
                         (int)sizeof(SMem));

    k_main<<<NCLS, TMAIN, sizeof(SMem)>>>(rois, delta, prob, iminfo, out);

    // k_final with programmatic dependent launch: its launch/prologue overlaps
    // k_main's tail; device-side cudaGridDependencySynchronize() provides the
    // ordering before it reads k_main's results.
    cudaLaunchConfig_t cfg = {};
    cfg.gridDim  = dim3(1, 1, 1);
    cfg.blockDim = dim3(TFIN, 1, 1);
    cfg.dynamicSmemBytes = 0;
    cfg.stream = 0;
    cudaLaunchAttribute attrs[1];
    attrs[0].id = cudaLaunchAttributeProgrammaticStreamSerialization;
    attrs[0].val.programmaticStreamSerializationAllowed = 1;
    cfg.attrs = attrs;
    cfg.numAttrs = 1;
    cudaLaunchKernelEx(&cfg, k_final, out);
}